// round 1
// baseline (speedup 1.0000x reference)
#include <cuda_runtime.h>
#include <math.h>

// Problem constants
#define HN 16
#define DHD 64
#define DD 1024
#define BB 2
#define SS 2048
#define MROWS (BB * SS)   // 4096

// Scratch (allocation-free rule: __device__ globals)
__device__ float g_q[BB * HN * SS * DHD];
__device__ float g_k[BB * HN * SS * DHD];
__device__ float g_v[BB * HN * SS * DHD];
__device__ float g_ctx[BB * SS * DD];

// ---------------------------------------------------------------------------
// Tiled GEMM: Y[M,N] = X[M,K] @ W[K,N] + bias[N]
// M=4096, N=1024, K=1024. 64x64 output tile, 256 threads, 4x4 per thread.
// OUT_BHSD=1: write Y remapped to [B,H,S,DH] (for Q/K/V); 0: row-major.
// ---------------------------------------------------------------------------
template <int OUT_BHSD>
__global__ __launch_bounds__(256)
void gemm_bias_kernel(const float* __restrict__ X,
                      const float* __restrict__ W,
                      const float* __restrict__ bias,
                      float* __restrict__ Y) {
    __shared__ float Xs[16][64];  // [k][m] (transposed for float4 reads)
    __shared__ float Ws[16][64];  // [k][n]

    const int tx = threadIdx.x & 15;
    const int ty = threadIdx.x >> 4;
    const int tid = threadIdx.x;
    const int n0 = blockIdx.x * 64;
    const int m0 = blockIdx.y * 64;

    float acc[4][4];
#pragma unroll
    for (int i = 0; i < 4; i++)
#pragma unroll
        for (int j = 0; j < 4; j++) acc[i][j] = 0.0f;

    // load indices
    const int xr = tid >> 2;            // 0..63  (m within tile)
    const int xc = (tid & 3) * 4;       // 0..12  (k within tile)
    const int wr = tid >> 4;            // 0..15  (k within tile)
    const int wc = (tid & 15) * 4;      // 0..60  (n within tile)

    for (int k0 = 0; k0 < DD; k0 += 16) {
        // X tile: rows m0..m0+63, cols k0..k0+15 -> transposed into Xs[k][m]
        float4 xv = *reinterpret_cast<const float4*>(&X[(size_t)(m0 + xr) * DD + k0 + xc]);
        Xs[xc + 0][xr] = xv.x;
        Xs[xc + 1][xr] = xv.y;
        Xs[xc + 2][xr] = xv.z;
        Xs[xc + 3][xr] = xv.w;
        // W tile: rows k0..k0+15, cols n0..n0+63 -> Ws[k][n]
        *reinterpret_cast<float4*>(&Ws[wr][wc]) =
            *reinterpret_cast<const float4*>(&W[(size_t)(k0 + wr) * DD + n0 + wc]);
        __syncthreads();

#pragma unroll
        for (int kk = 0; kk < 16; kk++) {
            float4 a = *reinterpret_cast<const float4*>(&Xs[kk][4 * ty]);
            float4 b = *reinterpret_cast<const float4*>(&Ws[kk][4 * tx]);
            float av[4] = {a.x, a.y, a.z, a.w};
            float bv[4] = {b.x, b.y, b.z, b.w};
#pragma unroll
            for (int i = 0; i < 4; i++)
#pragma unroll
                for (int j = 0; j < 4; j++) acc[i][j] += av[i] * bv[j];
        }
        __syncthreads();
    }

    // epilogue: bias + store (float4 per row)
    const int colBase = n0 + 4 * tx;
    float4 bv4 = *reinterpret_cast<const float4*>(&bias[colBase]);
    float bb4[4] = {bv4.x, bv4.y, bv4.z, bv4.w};

#pragma unroll
    for (int i = 0; i < 4; i++) {
        int row = m0 + 4 * ty + i;  // = b*S + s
        float4 out;
        out.x = acc[i][0] + bb4[0];
        out.y = acc[i][1] + bb4[1];
        out.z = acc[i][2] + bb4[2];
        out.w = acc[i][3] + bb4[3];
        if (OUT_BHSD) {
            int bidx = row >> 11;          // /S (S=2048)
            int sidx = row & (SS - 1);
            int h = colBase >> 6;          // /DH
            int dh = colBase & (DHD - 1);
            size_t idx = (((size_t)bidx * HN + h) * SS + sidx) * DHD + dh;
            *reinterpret_cast<float4*>(&g_q[0] + (Y - g_q) + idx) = out;  // Y already points at target scratch
        } else {
            *reinterpret_cast<float4*>(&Y[(size_t)row * DD + colBase]) = out;
        }
    }
}

// ---------------------------------------------------------------------------
// Flash attention (causal), per (b, h, 64-query tile).
// Q,K transposed in smem ([d][row]) for float4 reads; V row-major.
// K smem buffer is reused for P (scores no longer need K after QK^T).
// 256 threads, 4x4 per thread. Static smem = 3*16KB = 48KB.
// ---------------------------------------------------------------------------
__global__ __launch_bounds__(256)
void attn_kernel() {
    __shared__ float Qt[64][64];   // [d][q]
    __shared__ float KPt[64][64];  // K: [d][k]  then reused as P: [k][q]
    __shared__ float Vs[64][64];   // [k][d]

    const int tid = threadIdx.x;
    const int tx = tid & 15;
    const int ty = tid >> 4;
    const int qt = blockIdx.x;     // 0..31
    const int h = blockIdx.y;
    const int b = blockIdx.z;
    const int q0 = qt * 64;

    const size_t head_base = (((size_t)b * HN + h) * SS) * DHD;

    // Load Q tile transposed: Qt[d][q]
    {
        const float* Qg = g_q + head_base + (size_t)q0 * DHD;
#pragma unroll
        for (int it = 0; it < 4; it++) {
            int idx = tid + it * 256;       // 0..1023 float4s
            int r = idx >> 4;               // q row 0..63
            int c = (idx & 15) * 4;         // d 0..60
            float4 v = *reinterpret_cast<const float4*>(&Qg[(size_t)r * DHD + c]);
            Qt[c + 0][r] = v.x;
            Qt[c + 1][r] = v.y;
            Qt[c + 2][r] = v.z;
            Qt[c + 3][r] = v.w;
        }
    }

    float m[4], l[4], o[4][4];
#pragma unroll
    for (int i = 0; i < 4; i++) {
        m[i] = -INFINITY;
        l[i] = 0.0f;
#pragma unroll
        for (int j = 0; j < 4; j++) o[i][j] = 0.0f;
    }

    for (int kt = 0; kt <= qt; kt++) {
        __syncthreads();  // previous iter's smem reads done
        // Load K tile transposed (KPt[d][k]) and V tile row-major
        const float* Kg = g_k + head_base + (size_t)(kt * 64) * DHD;
        const float* Vg = g_v + head_base + (size_t)(kt * 64) * DHD;
#pragma unroll
        for (int it = 0; it < 4; it++) {
            int idx = tid + it * 256;
            int r = idx >> 4;
            int c = (idx & 15) * 4;
            float4 v = *reinterpret_cast<const float4*>(&Kg[(size_t)r * DHD + c]);
            KPt[c + 0][r] = v.x;
            KPt[c + 1][r] = v.y;
            KPt[c + 2][r] = v.z;
            KPt[c + 3][r] = v.w;
            *reinterpret_cast<float4*>(&Vs[r][c]) =
                *reinterpret_cast<const float4*>(&Vg[(size_t)r * DHD + c]);
        }
        __syncthreads();

        // scores s[i][j] = sum_d Qt[d][4ty+i] * KPt[d][4tx+j]
        float s[4][4];
#pragma unroll
        for (int i = 0; i < 4; i++)
#pragma unroll
            for (int j = 0; j < 4; j++) s[i][j] = 0.0f;
#pragma unroll 8
        for (int dd = 0; dd < 64; dd++) {
            float4 a = *reinterpret_cast<const float4*>(&Qt[dd][4 * ty]);
            float4 bq = *reinterpret_cast<const float4*>(&KPt[dd][4 * tx]);
            float av[4] = {a.x, a.y, a.z, a.w};
            float bv[4] = {bq.x, bq.y, bq.z, bq.w};
#pragma unroll
            for (int i = 0; i < 4; i++)
#pragma unroll
                for (int j = 0; j < 4; j++) s[i][j] += av[i] * bv[j];
        }
        __syncthreads();  // K reads done; KPt can be reused for P

        // scale + causal mask (only the diagonal tile needs masking)
        const bool diag = (kt == qt);
#pragma unroll
        for (int i = 0; i < 4; i++) {
#pragma unroll
            for (int j = 0; j < 4; j++) {
                s[i][j] *= 0.125f;
                if (diag && (4 * tx + j) > (4 * ty + i)) s[i][j] = -INFINITY;
            }
        }

        // online softmax: row reductions across tx (shuffle width 16)
        float pr[4][4];
#pragma unroll
        for (int i = 0; i < 4; i++) {
            float rm = fmaxf(fmaxf(s[i][0], s[i][1]), fmaxf(s[i][2], s[i][3]));
#pragma unroll
            for (int off = 8; off >= 1; off >>= 1)
                rm = fmaxf(rm, __shfl_xor_sync(0xffffffffu, rm, off, 16));
            float mn = fmaxf(m[i], rm);
            float alpha = __expf(m[i] - mn);  // exp(-inf)=0 on first tile
            float rs = 0.0f;
#pragma unroll
            for (int j = 0; j < 4; j++) {
                float p = __expf(s[i][j] - mn);
                pr[i][j] = p;
                rs += p;
            }
#pragma unroll
            for (int off = 8; off >= 1; off >>= 1)
                rs += __shfl_xor_sync(0xffffffffu, rs, off, 16);
            l[i] = l[i] * alpha + rs;
            m[i] = mn;
#pragma unroll
            for (int j = 0; j < 4; j++) o[i][j] *= alpha;
        }

        // store P transposed into KPt: P[k][q]
#pragma unroll
        for (int i = 0; i < 4; i++)
#pragma unroll
            for (int j = 0; j < 4; j++) KPt[4 * tx + j][4 * ty + i] = pr[i][j];
        __syncthreads();

        // o[i][j] += sum_k P[k][4ty+i] * V[k][4tx+j]
#pragma unroll 8
        for (int kk = 0; kk < 64; kk++) {
            float4 a = *reinterpret_cast<const float4*>(&KPt[kk][4 * ty]);
            float4 bvv = *reinterpret_cast<const float4*>(&Vs[kk][4 * tx]);
            float av[4] = {a.x, a.y, a.z, a.w};
            float bv[4] = {bvv.x, bvv.y, bvv.z, bvv.w};
#pragma unroll
            for (int i = 0; i < 4; i++)
#pragma unroll
                for (int j = 0; j < 4; j++) o[i][j] += av[i] * bv[j];
        }
    }

    // epilogue: normalize and write ctx in [B,S,D] layout
#pragma unroll
    for (int i = 0; i < 4; i++) {
        float inv = 1.0f / l[i];
        int srow = q0 + 4 * ty + i;
        float4 out;
        out.x = o[i][0] * inv;
        out.y = o[i][1] * inv;
        out.z = o[i][2] * inv;
        out.w = o[i][3] * inv;
        size_t idx = ((size_t)b * SS + srow) * DD + h * DHD + 4 * tx;
        *reinterpret_cast<float4*>(&g_ctx[idx]) = out;
    }
}

// ---------------------------------------------------------------------------
extern "C" void kernel_launch(void* const* d_in, const int* in_sizes, int n_in,
                              void* d_out, int out_size) {
    const float* x  = (const float*)d_in[0];
    const float* Wq = (const float*)d_in[1];
    const float* bq = (const float*)d_in[2];
    const float* Wk = (const float*)d_in[3];
    const float* bk = (const float*)d_in[4];
    const float* Wv = (const float*)d_in[5];
    const float* bv = (const float*)d_in[6];
    const float* Wo = (const float*)d_in[7];
    const float* bo = (const float*)d_in[8];
    float* out = (float*)d_out;

    float *pq, *pk, *pv, *pctx;
    cudaGetSymbolAddress((void**)&pq, g_q);
    cudaGetSymbolAddress((void**)&pk, g_k);
    cudaGetSymbolAddress((void**)&pv, g_v);
    cudaGetSymbolAddress((void**)&pctx, g_ctx);

    dim3 gblk(256);
    dim3 ggrid(DD / 64, MROWS / 64);  // (16, 64)

    gemm_bias_kernel<1><<<ggrid, gblk>>>(x, Wq, bq, pq);
    gemm_bias_kernel<1><<<ggrid, gblk>>>(x, Wk, bk, pk);
    gemm_bias_kernel<1><<<ggrid, gblk>>>(x, Wv, bv, pv);

    dim3 agrid(SS / 64, HN, BB);  // (32, 16, 2)
    attn_kernel<<<agrid, gblk>>>();

    gemm_bias_kernel<0><<<ggrid, gblk>>>(pctx, Wo, bo, out);
}

// round 3
// speedup vs baseline: 1.9724x; 1.9724x over previous
#include <cuda_runtime.h>
#include <cuda_bf16.h>
#include <math.h>
#include <stdint.h>

#define HN 16
#define DHD 64
#define DD 1024
#define BB 2
#define SS 2048
#define MROWS (BB * SS)   // 4096

// ------------------------- device scratch (no allocs) -----------------------
__device__ __align__(16) __nv_bfloat16 g_xh[MROWS * DD];
__device__ __align__(16) __nv_bfloat16 g_xl[MROWS * DD];
__device__ __align__(16) __nv_bfloat16 g_wht[4][DD * DD];  // [N][K] hi
__device__ __align__(16) __nv_bfloat16 g_wlt[4][DD * DD];  // [N][K] lo
__device__ __align__(16) float g_q[BB * HN * SS * DHD];
__device__ __align__(16) float g_k[BB * HN * SS * DHD];
__device__ __align__(16) float g_v[BB * HN * SS * DHD];
__device__ __align__(16) __nv_bfloat16 g_ch[MROWS * DD];
__device__ __align__(16) __nv_bfloat16 g_cl[MROWS * DD];

// ------------------------------ ptx helpers --------------------------------
__device__ __forceinline__ uint32_t smem_u32(const void* p) {
    return (uint32_t)__cvta_generic_to_shared(p);
}
__device__ __forceinline__ void cpa16(uint32_t d, const void* s) {
    asm volatile("cp.async.cg.shared.global [%0], [%1], 16;" :: "r"(d), "l"(s));
}
__device__ __forceinline__ void cpa_commit() {
    asm volatile("cp.async.commit_group;" ::: "memory");
}
__device__ __forceinline__ void ldsm_x4(uint32_t& d0, uint32_t& d1, uint32_t& d2,
                                        uint32_t& d3, uint32_t addr) {
    asm volatile("ldmatrix.sync.aligned.m8n8.x4.shared.b16 {%0,%1,%2,%3}, [%4];"
                 : "=r"(d0), "=r"(d1), "=r"(d2), "=r"(d3) : "r"(addr));
}
__device__ __forceinline__ void mma_bf16(float* c, const uint32_t* a,
                                         uint32_t b0, uint32_t b1) {
    asm volatile(
        "mma.sync.aligned.m16n8k16.row.col.f32.bf16.bf16.f32 "
        "{%0,%1,%2,%3}, {%4,%5,%6,%7}, {%8,%9}, {%0,%1,%2,%3};"
        : "+f"(c[0]), "+f"(c[1]), "+f"(c[2]), "+f"(c[3])
        : "r"(a[0]), "r"(a[1]), "r"(a[2]), "r"(a[3]), "r"(b0), "r"(b1));
}

// ---------------------------- conversion kernels ---------------------------
__global__ __launch_bounds__(256)
void convert_x_kernel(const float* __restrict__ X,
                      __nv_bfloat16* __restrict__ Xh,
                      __nv_bfloat16* __restrict__ Xl) {
    size_t i = (size_t)blockIdx.x * blockDim.x + threadIdx.x;  // float4 index
    float4 v = reinterpret_cast<const float4*>(X)[i];
    float f[4] = {v.x, v.y, v.z, v.w};
    __nv_bfloat162 hh[2], ll[2];
#pragma unroll
    for (int j = 0; j < 2; j++) {
        __nv_bfloat16 h0 = __float2bfloat16(f[2 * j]);
        __nv_bfloat16 h1 = __float2bfloat16(f[2 * j + 1]);
        hh[j].x = h0; hh[j].y = h1;
        ll[j].x = __float2bfloat16(f[2 * j] - __bfloat162float(h0));
        ll[j].y = __float2bfloat16(f[2 * j + 1] - __bfloat162float(h1));
    }
    reinterpret_cast<__nv_bfloat162*>(Xh)[2 * i + 0] = hh[0];
    reinterpret_cast<__nv_bfloat162*>(Xh)[2 * i + 1] = hh[1];
    reinterpret_cast<__nv_bfloat162*>(Xl)[2 * i + 0] = ll[0];
    reinterpret_cast<__nv_bfloat162*>(Xl)[2 * i + 1] = ll[1];
}

// W [K,N] fp32 -> WhT, WlT [N,K] bf16 (transpose + split)
__global__ __launch_bounds__(256)
void convert_wT_kernel(const float* __restrict__ W,
                       __nv_bfloat16* __restrict__ WhT,
                       __nv_bfloat16* __restrict__ WlT) {
    __shared__ float t[32][33];
    int n0 = blockIdx.x * 32, k0 = blockIdx.y * 32;
    int tx = threadIdx.x & 31;
    int ty = threadIdx.x >> 5;  // 0..7
#pragma unroll
    for (int j = 0; j < 4; j++)
        t[ty + 8 * j][tx] = W[(size_t)(k0 + ty + 8 * j) * DD + n0 + tx];
    __syncthreads();
#pragma unroll
    for (int j = 0; j < 4; j++) {
        float v = t[tx][ty + 8 * j];  // W[k0+tx][n0+ty+8j]
        __nv_bfloat16 h = __float2bfloat16(v);
        size_t o = (size_t)(n0 + ty + 8 * j) * DD + k0 + tx;
        WhT[o] = h;
        WlT[o] = __float2bfloat16(v - __bfloat162float(h));
    }
}

// ------------------------- mma.sync bf16x3 GEMM -----------------------------
// Y[4096,1024] = (Ah+Al)[M,K] @ (Bh+Bl)^T (B stored [N][K]) + bias
// CTA 128x128, BK=32, 8 warps (4m x 2n), warp tile 32x64.
#define BM 128
#define BN 128
#define BK 32
#define NCH (DD / BK)       // 32
#define MAT_B (BM * BK * 2) // 8192 bytes per matrix tile
#define STG_B (4 * MAT_B)   // 32768 per stage (Ah, Al, Bh, Bl)
#define GEMM_SMEM (2 * STG_B)

// smem offset of (row, 16B-chunk) with XOR swizzle; row stride 64B (32 bf16)
__device__ __forceinline__ uint32_t soff(int r, int c) {
    return (uint32_t)(r * 64 + ((c ^ ((r >> 1) & 3)) << 4));
}

__device__ __forceinline__ void load_stage(uint32_t sb,
                                           const __nv_bfloat16* Ah, const __nv_bfloat16* Al,
                                           const __nv_bfloat16* Bh, const __nv_bfloat16* Bl,
                                           int m0, int n0, int chunk, int tid) {
    const int kb = chunk * BK;
#pragma unroll
    for (int t = 0; t < 8; t++) {
        int idx = t * 256 + tid;        // 0..2047
        int mat = idx >> 9;             // 0..3
        int i = idx & 511;
        int r = i >> 2;                 // 0..127
        int c = i & 3;                  // 16B chunk
        uint32_t d = sb + mat * MAT_B + soff(r, c);
        const __nv_bfloat16* src;
        if (mat == 0)      src = Ah + (size_t)(m0 + r) * DD + kb + c * 8;
        else if (mat == 1) src = Al + (size_t)(m0 + r) * DD + kb + c * 8;
        else if (mat == 2) src = Bh + (size_t)(n0 + r) * DD + kb + c * 8;
        else               src = Bl + (size_t)(n0 + r) * DD + kb + c * 8;
        cpa16(d, (const void*)src);
    }
    cpa_commit();
}

// MODE 0: row-major Y[M, DD]; MODE 1: scatter to [B,H,S,DH]
template <int MODE>
__global__ __launch_bounds__(256, 2)
void gemm_tc_kernel(const __nv_bfloat16* __restrict__ Ah, const __nv_bfloat16* __restrict__ Al,
                    const __nv_bfloat16* __restrict__ Bh, const __nv_bfloat16* __restrict__ Bl,
                    const float* __restrict__ bias, float* __restrict__ Y) {
    extern __shared__ char dsm[];
    const int tid = threadIdx.x;
    const int lane = tid & 31;
    const int wid = tid >> 5;
    const int mwarp = wid & 3;    // 0..3 -> m offset 32*mwarp
    const int nwarp = wid >> 2;   // 0..1 -> n offset 64*nwarp
    const int n0 = blockIdx.x * BN;
    const int m0 = blockIdx.y * BM;

    const uint32_t sbase = smem_u32(dsm);
    const int lr = lane & 7;
    const int lg = lane >> 3;     // ldmatrix group 0..3

    float acc[2][8][4];
#pragma unroll
    for (int mt = 0; mt < 2; mt++)
#pragma unroll
        for (int nt = 0; nt < 8; nt++)
#pragma unroll
            for (int r = 0; r < 4; r++) acc[mt][nt][r] = 0.0f;

    load_stage(sbase, Ah, Al, Bh, Bl, m0, n0, 0, tid);
    load_stage(sbase + STG_B, Ah, Al, Bh, Bl, m0, n0, 1, tid);

    for (int c = 0; c < NCH; c++) {
        if (c < NCH - 1) asm volatile("cp.async.wait_group 1;" ::: "memory");
        else             asm volatile("cp.async.wait_group 0;" ::: "memory");
        __syncthreads();

        const uint32_t sb = sbase + (uint32_t)(c & 1) * STG_B;
        const uint32_t sAh = sb;
        const uint32_t sAl = sb + MAT_B;
        const uint32_t sBh = sb + 2 * MAT_B;
        const uint32_t sBl = sb + 3 * MAT_B;

#pragma unroll
        for (int ks = 0; ks < 2; ks++) {
            const int c0 = ks * 2;   // 16B chunk base for this k16
            // A fragments: 2 m-tiles, hi and lo
            uint32_t ah[2][4], al[2][4];
#pragma unroll
            for (int mt = 0; mt < 2; mt++) {
                int row = mwarp * 32 + mt * 16 + lr + (lg & 1) * 8;
                int ch = c0 + (lg >> 1);
                uint32_t off = soff(row, ch);
                ldsm_x4(ah[mt][0], ah[mt][1], ah[mt][2], ah[mt][3], sAh + off);
                ldsm_x4(al[mt][0], al[mt][1], al[mt][2], al[mt][3], sAl + off);
            }
            // B: 4 n-pairs; each x4 gives two n-tiles' (b0,b1)
#pragma unroll
            for (int np = 0; np < 4; np++) {
                int brow = nwarp * 64 + np * 16 + lr + (lg >> 1) * 8;
                int bch = c0 + (lg & 1);
                uint32_t boff = soff(brow, bch);
                uint32_t bh0, bh1, bh2, bh3, bl0, bl1, bl2, bl3;
                ldsm_x4(bh0, bh1, bh2, bh3, sBh + boff);
                ldsm_x4(bl0, bl1, bl2, bl3, sBl + boff);
#pragma unroll
                for (int mt = 0; mt < 2; mt++) {
                    mma_bf16(acc[mt][2 * np + 0], ah[mt], bh0, bh1);
                    mma_bf16(acc[mt][2 * np + 1], ah[mt], bh2, bh3);
                    mma_bf16(acc[mt][2 * np + 0], ah[mt], bl0, bl1);
                    mma_bf16(acc[mt][2 * np + 1], ah[mt], bl2, bl3);
                    mma_bf16(acc[mt][2 * np + 0], al[mt], bh0, bh1);
                    mma_bf16(acc[mt][2 * np + 1], al[mt], bh2, bh3);
                }
            }
        }
        __syncthreads();
        if (c + 2 < NCH)
            load_stage(sb, Ah, Al, Bh, Bl, m0, n0, c + 2, tid);
    }

    // epilogue: acc[mt][nt][{c0,c1 | c2,c3}] -> rows (l>>2) and (l>>2)+8
    const int hh = (n0 + nwarp * 64) >> 6;  // head (MODE 1); 64-aligned per warp
#pragma unroll
    for (int mt = 0; mt < 2; mt++) {
#pragma unroll
        for (int half = 0; half < 2; half++) {
            int gm = m0 + mwarp * 32 + mt * 16 + (lane >> 2) + half * 8;
            size_t rowbase;
            if (MODE == 1) {
                int bidx = gm >> 11;
                int sidx = gm & (SS - 1);
                rowbase = (((size_t)bidx * HN + hh) * SS + sidx) * DHD;
            } else {
                rowbase = (size_t)gm * DD;
            }
#pragma unroll
            for (int nt = 0; nt < 8; nt++) {
                int ncol = n0 + nwarp * 64 + nt * 8 + 2 * (lane & 3);
                float2 bv = *reinterpret_cast<const float2*>(&bias[ncol]);
                float2 o;
                o.x = acc[mt][nt][2 * half + 0] + bv.x;
                o.y = acc[mt][nt][2 * half + 1] + bv.y;
                size_t col = (MODE == 1) ? (size_t)(ncol & (DHD - 1)) : (size_t)ncol;
                *reinterpret_cast<float2*>(&Y[rowbase + col]) = o;
            }
        }
    }
}

// ---------------------- flash attention (swizzled smem) --------------------
__global__ __launch_bounds__(256)
void attn_kernel() {
    __shared__ float Qt[64][64];   // [d][swz(q)]
    __shared__ float KPt[64][64];  // K: [d][swz(k)] then P: [k][swz(q)]
    __shared__ float Vs[64][64];   // [k][d]

    const int tid = threadIdx.x;
    const int tx = tid & 15;
    const int ty = tid >> 4;
    const int qt = blockIdx.x;
    const int h = blockIdx.y;
    const int b = blockIdx.z;
    const int q0 = qt * 64;

    const size_t head_base = (((size_t)b * HN + h) * SS) * DHD;

    {   // load Q transposed with swizzle
        const float* Qg = g_q + head_base + (size_t)q0 * DHD;
#pragma unroll
        for (int it = 0; it < 4; it++) {
            int idx = tid + it * 256;
            int r = idx >> 4;
            int sw = idx & 15;               // = c>>2
            int c = sw * 4;
            float4 v = *reinterpret_cast<const float4*>(&Qg[(size_t)r * DHD + c]);
            int qs = 4 * ((r >> 2) ^ sw) + (r & 3);
            Qt[c + 0][qs] = v.x;
            Qt[c + 1][qs] = v.y;
            Qt[c + 2][qs] = v.z;
            Qt[c + 3][qs] = v.w;
        }
    }

    float m[4], l[4], o[4][4];
#pragma unroll
    for (int i = 0; i < 4; i++) {
        m[i] = -INFINITY;
        l[i] = 0.0f;
#pragma unroll
        for (int j = 0; j < 4; j++) o[i][j] = 0.0f;
    }

    for (int kt = 0; kt <= qt; kt++) {
        __syncthreads();
        const float* Kg = g_k + head_base + (size_t)(kt * 64) * DHD;
        const float* Vg = g_v + head_base + (size_t)(kt * 64) * DHD;
#pragma unroll
        for (int it = 0; it < 4; it++) {
            int idx = tid + it * 256;
            int r = idx >> 4;
            int sw = idx & 15;
            int c = sw * 4;
            float4 v = *reinterpret_cast<const float4*>(&Kg[(size_t)r * DHD + c]);
            int ks = 4 * ((r >> 2) ^ sw) + (r & 3);
            KPt[c + 0][ks] = v.x;
            KPt[c + 1][ks] = v.y;
            KPt[c + 2][ks] = v.z;
            KPt[c + 3][ks] = v.w;
            *reinterpret_cast<float4*>(&Vs[r][c]) =
                *reinterpret_cast<const float4*>(&Vg[(size_t)r * DHD + c]);
        }
        __syncthreads();

        float s[4][4];
#pragma unroll
        for (int i = 0; i < 4; i++)
#pragma unroll
            for (int j = 0; j < 4; j++) s[i][j] = 0.0f;
#pragma unroll 8
        for (int dd = 0; dd < 64; dd++) {
            int sw = (dd >> 2) & 15;
            float4 a = *reinterpret_cast<const float4*>(&Qt[dd][4 * (ty ^ sw)]);
            float4 bq = *reinterpret_cast<const float4*>(&KPt[dd][4 * (tx ^ sw)]);
            float av[4] = {a.x, a.y, a.z, a.w};
            float bv[4] = {bq.x, bq.y, bq.z, bq.w};
#pragma unroll
            for (int i = 0; i < 4; i++)
#pragma unroll
                for (int j = 0; j < 4; j++) s[i][j] += av[i] * bv[j];
        }
        __syncthreads();  // KPt reuse for P

        const bool diag = (kt == qt);
#pragma unroll
        for (int i = 0; i < 4; i++) {
#pragma unroll
            for (int j = 0; j < 4; j++) {
                s[i][j] *= 0.125f;
                if (diag && (4 * tx + j) > (4 * ty + i)) s[i][j] = -INFINITY;
            }
        }

        float pr[4][4];
#pragma unroll
        for (int i = 0; i < 4; i++) {
            float rm = fmaxf(fmaxf(s[i][0], s[i][1]), fmaxf(s[i][2], s[i][3]));
#pragma unroll
            for (int off = 8; off >= 1; off >>= 1)
                rm = fmaxf(rm, __shfl_xor_sync(0xffffffffu, rm, off, 16));
            float mn = fmaxf(m[i], rm);
            float alpha = __expf(m[i] - mn);
            float rs = 0.0f;
#pragma unroll
            for (int j = 0; j < 4; j++) {
                float p = __expf(s[i][j] - mn);
                pr[i][j] = p;
                rs += p;
            }
#pragma unroll
            for (int off = 8; off >= 1; off >>= 1)
                rs += __shfl_xor_sync(0xffffffffu, rs, off, 16);
            l[i] = l[i] * alpha + rs;
            m[i] = mn;
#pragma unroll
            for (int j = 0; j < 4; j++) o[i][j] *= alpha;
        }

        // P[k][swz(q)] with swizzle s = k>>2 = tx
#pragma unroll
        for (int i = 0; i < 4; i++)
#pragma unroll
            for (int j = 0; j < 4; j++)
                KPt[4 * tx + j][4 * (ty ^ tx) + i] = pr[i][j];
        __syncthreads();

#pragma unroll 8
        for (int kk = 0; kk < 64; kk++) {
            int sw = (kk >> 2) & 15;
            float4 a = *reinterpret_cast<const float4*>(&KPt[kk][4 * (ty ^ sw)]);
            float4 bvv = *reinterpret_cast<const float4*>(&Vs[kk][4 * tx]);
            float av[4] = {a.x, a.y, a.z, a.w};
            float bv[4] = {bvv.x, bvv.y, bvv.z, bvv.w};
#pragma unroll
            for (int i = 0; i < 4; i++)
#pragma unroll
                for (int j = 0; j < 4; j++) o[i][j] += av[i] * bv[j];
        }
    }

    // epilogue: normalize, split to bf16 hi/lo ctx
#pragma unroll
    for (int i = 0; i < 4; i++) {
        float inv = 1.0f / l[i];
        int srow = q0 + 4 * ty + i;
        float f[4];
#pragma unroll
        for (int j = 0; j < 4; j++) f[j] = o[i][j] * inv;
        size_t cidx = ((size_t)b * SS + srow) * DD + h * DHD + 4 * tx;
        __nv_bfloat162 hh[2], ll[2];
#pragma unroll
        for (int j = 0; j < 2; j++) {
            __nv_bfloat16 h0 = __float2bfloat16(f[2 * j]);
            __nv_bfloat16 h1 = __float2bfloat16(f[2 * j + 1]);
            hh[j].x = h0; hh[j].y = h1;
            ll[j].x = __float2bfloat16(f[2 * j] - __bfloat162float(h0));
            ll[j].y = __float2bfloat16(f[2 * j + 1] - __bfloat162float(h1));
        }
        *reinterpret_cast<__nv_bfloat162*>(&g_ch[cidx + 0]) = hh[0];
        *reinterpret_cast<__nv_bfloat162*>(&g_ch[cidx + 2]) = hh[1];
        *reinterpret_cast<__nv_bfloat162*>(&g_cl[cidx + 0]) = ll[0];
        *reinterpret_cast<__nv_bfloat162*>(&g_cl[cidx + 2]) = ll[1];
    }
}

// ---------------------------------------------------------------------------
extern "C" void kernel_launch(void* const* d_in, const int* in_sizes, int n_in,
                              void* d_out, int out_size) {
    const float* x  = (const float*)d_in[0];
    const float* Wq = (const float*)d_in[1];
    const float* bq = (const float*)d_in[2];
    const float* Wk = (const float*)d_in[3];
    const float* bk = (const float*)d_in[4];
    const float* Wv = (const float*)d_in[5];
    const float* bv = (const float*)d_in[6];
    const float* Wo = (const float*)d_in[7];
    const float* bo = (const float*)d_in[8];
    float* out = (float*)d_out;

    __nv_bfloat16 *pxh, *pxl, *pwht, *pwlt, *pch, *pcl;
    float *pq, *pk, *pv;
    cudaGetSymbolAddress((void**)&pxh, g_xh);
    cudaGetSymbolAddress((void**)&pxl, g_xl);
    cudaGetSymbolAddress((void**)&pwht, g_wht);
    cudaGetSymbolAddress((void**)&pwlt, g_wlt);
    cudaGetSymbolAddress((void**)&pq, g_q);
    cudaGetSymbolAddress((void**)&pk, g_k);
    cudaGetSymbolAddress((void**)&pv, g_v);
    cudaGetSymbolAddress((void**)&pch, g_ch);
    cudaGetSymbolAddress((void**)&pcl, g_cl);

    cudaFuncSetAttribute(gemm_tc_kernel<0>, cudaFuncAttributeMaxDynamicSharedMemorySize, GEMM_SMEM);
    cudaFuncSetAttribute(gemm_tc_kernel<1>, cudaFuncAttributeMaxDynamicSharedMemorySize, GEMM_SMEM);

    // 1) split X into bf16 hi/lo
    convert_x_kernel<<<(MROWS * DD / 4) / 256, 256>>>(x, pxh, pxl);

    // 2) transpose+split weights
    dim3 tgrid(DD / 32, DD / 32);
    convert_wT_kernel<<<tgrid, 256>>>(Wq, pwht + 0 * DD * DD, pwlt + 0 * DD * DD);
    convert_wT_kernel<<<tgrid, 256>>>(Wk, pwht + 1 * DD * DD, pwlt + 1 * DD * DD);
    convert_wT_kernel<<<tgrid, 256>>>(Wv, pwht + 2 * DD * DD, pwlt + 2 * DD * DD);
    convert_wT_kernel<<<tgrid, 256>>>(Wo, pwht + 3 * DD * DD, pwlt + 3 * DD * DD);

    // 3) Q/K/V projections (mma.sync), scattered to [B,H,S,DH]
    dim3 ggrid(DD / BN, MROWS / BM);  // (8, 32)
    gemm_tc_kernel<1><<<ggrid, 256, GEMM_SMEM>>>(pxh, pxl, pwht + 0 * DD * DD, pwlt + 0 * DD * DD, bq, pq);
    gemm_tc_kernel<1><<<ggrid, 256, GEMM_SMEM>>>(pxh, pxl, pwht + 1 * DD * DD, pwlt + 1 * DD * DD, bk, pk);
    gemm_tc_kernel<1><<<ggrid, 256, GEMM_SMEM>>>(pxh, pxl, pwht + 2 * DD * DD, pwlt + 2 * DD * DD, bv, pv);

    // 4) attention (writes ctx as bf16 hi/lo)
    dim3 agrid(SS / 64, HN, BB);
    attn_kernel<<<agrid, 256>>>();

    // 5) output projection
    gemm_tc_kernel<0><<<ggrid, 256, GEMM_SMEM>>>(pch, pcl, pwht + 3 * DD * DD, pwlt + 3 * DD * DD, bo, out);
}

// round 4
// speedup vs baseline: 3.5867x; 1.8184x over previous
#include <cuda_runtime.h>
#include <cuda_bf16.h>
#include <math.h>
#include <stdint.h>

#define HN 16
#define DHD 64
#define DD 1024
#define BB 2
#define SS 2048
#define MROWS (BB * SS)   // 4096

// ------------------------- device scratch (no allocs) -----------------------
__device__ __align__(16) __nv_bfloat16 g_xh[MROWS * DD];
__device__ __align__(16) __nv_bfloat16 g_xl[MROWS * DD];
__device__ __align__(16) __nv_bfloat16 g_wht[4][DD * DD];  // [N][K] hi
__device__ __align__(16) __nv_bfloat16 g_wlt[4][DD * DD];  // [N][K] lo
// Q/K: [b,h,s,dh] bf16 hi/lo (Q pre-scaled by 0.125); V transposed: [b,h,dh,s]
__device__ __align__(16) __nv_bfloat16 g_qh[BB * HN * SS * DHD];
__device__ __align__(16) __nv_bfloat16 g_ql[BB * HN * SS * DHD];
__device__ __align__(16) __nv_bfloat16 g_kh[BB * HN * SS * DHD];
__device__ __align__(16) __nv_bfloat16 g_kl[BB * HN * SS * DHD];
__device__ __align__(16) __nv_bfloat16 g_vth[BB * HN * SS * DHD];
__device__ __align__(16) __nv_bfloat16 g_vtl[BB * HN * SS * DHD];
__device__ __align__(16) __nv_bfloat16 g_ch[MROWS * DD];
__device__ __align__(16) __nv_bfloat16 g_cl[MROWS * DD];

// ------------------------------ ptx helpers --------------------------------
__device__ __forceinline__ uint32_t smem_u32(const void* p) {
    return (uint32_t)__cvta_generic_to_shared(p);
}
__device__ __forceinline__ void cpa16(uint32_t d, const void* s) {
    asm volatile("cp.async.cg.shared.global [%0], [%1], 16;" :: "r"(d), "l"(s));
}
__device__ __forceinline__ void cpa_commit() {
    asm volatile("cp.async.commit_group;" ::: "memory");
}
__device__ __forceinline__ void ldsm_x4(uint32_t& d0, uint32_t& d1, uint32_t& d2,
                                        uint32_t& d3, uint32_t addr) {
    asm volatile("ldmatrix.sync.aligned.m8n8.x4.shared.b16 {%0,%1,%2,%3}, [%4];"
                 : "=r"(d0), "=r"(d1), "=r"(d2), "=r"(d3) : "r"(addr));
}
__device__ __forceinline__ void mma_bf16(float* c, const uint32_t* a,
                                         uint32_t b0, uint32_t b1) {
    asm volatile(
        "mma.sync.aligned.m16n8k16.row.col.f32.bf16.bf16.f32 "
        "{%0,%1,%2,%3}, {%4,%5,%6,%7}, {%8,%9}, {%0,%1,%2,%3};"
        : "+f"(c[0]), "+f"(c[1]), "+f"(c[2]), "+f"(c[3])
        : "r"(a[0]), "r"(a[1]), "r"(a[2]), "r"(a[3]), "r"(b0), "r"(b1));
}
// split float2 -> bf16x2 hi + bf16x2 lo (packed u32)
__device__ __forceinline__ void split2(float x, float y, uint32_t& h, uint32_t& l) {
    __nv_bfloat162 bh = __floats2bfloat162_rn(x, y);
    __nv_bfloat162 bl = __floats2bfloat162_rn(x - __bfloat162float(bh.x),
                                              y - __bfloat162float(bh.y));
    h = *reinterpret_cast<uint32_t*>(&bh);
    l = *reinterpret_cast<uint32_t*>(&bl);
}

// ---------------------------- conversion kernels ---------------------------
__global__ __launch_bounds__(256)
void convert_x_kernel(const float* __restrict__ X,
                      __nv_bfloat16* __restrict__ Xh,
                      __nv_bfloat16* __restrict__ Xl) {
    size_t i = (size_t)blockIdx.x * blockDim.x + threadIdx.x;
    float4 v = reinterpret_cast<const float4*>(X)[i];
    uint32_t h0, l0, h1, l1;
    split2(v.x, v.y, h0, l0);
    split2(v.z, v.w, h1, l1);
    reinterpret_cast<uint32_t*>(Xh)[2 * i + 0] = h0;
    reinterpret_cast<uint32_t*>(Xh)[2 * i + 1] = h1;
    reinterpret_cast<uint32_t*>(Xl)[2 * i + 0] = l0;
    reinterpret_cast<uint32_t*>(Xl)[2 * i + 1] = l1;
}

__global__ __launch_bounds__(256)
void convert_wT_kernel(const float* __restrict__ W,
                       __nv_bfloat16* __restrict__ WhT,
                       __nv_bfloat16* __restrict__ WlT) {
    __shared__ float t[32][33];
    int n0 = blockIdx.x * 32, k0 = blockIdx.y * 32;
    int tx = threadIdx.x & 31;
    int ty = threadIdx.x >> 5;
#pragma unroll
    for (int j = 0; j < 4; j++)
        t[ty + 8 * j][tx] = W[(size_t)(k0 + ty + 8 * j) * DD + n0 + tx];
    __syncthreads();
#pragma unroll
    for (int j = 0; j < 4; j++) {
        float v = t[tx][ty + 8 * j];
        __nv_bfloat16 h = __float2bfloat16(v);
        size_t o = (size_t)(n0 + ty + 8 * j) * DD + k0 + tx;
        WhT[o] = h;
        WlT[o] = __float2bfloat16(v - __bfloat162float(h));
    }
}

// ------------------------- mma.sync bf16x3 GEMM -----------------------------
#define BM 128
#define BN 128
#define BK 32
#define NCH (DD / BK)
#define MAT_B (BM * BK * 2)
#define STG_B (4 * MAT_B)
#define GEMM_SMEM (2 * STG_B)

__device__ __forceinline__ uint32_t soff(int r, int c) {  // 64B rows, 4 chunks
    return (uint32_t)(r * 64 + ((c ^ ((r >> 1) & 3)) << 4));
}

__device__ __forceinline__ void load_stage(uint32_t sb,
                                           const __nv_bfloat16* Ah, const __nv_bfloat16* Al,
                                           const __nv_bfloat16* Bh, const __nv_bfloat16* Bl,
                                           int m0, int n0, int chunk, int tid) {
    const int kb = chunk * BK;
#pragma unroll
    for (int t = 0; t < 8; t++) {
        int idx = t * 256 + tid;
        int mat = idx >> 9;
        int i = idx & 511;
        int r = i >> 2;
        int c = i & 3;
        uint32_t d = sb + mat * MAT_B + soff(r, c);
        const __nv_bfloat16* src;
        if (mat == 0)      src = Ah + (size_t)(m0 + r) * DD + kb + c * 8;
        else if (mat == 1) src = Al + (size_t)(m0 + r) * DD + kb + c * 8;
        else if (mat == 2) src = Bh + (size_t)(n0 + r) * DD + kb + c * 8;
        else               src = Bl + (size_t)(n0 + r) * DD + kb + c * 8;
        cpa16(d, (const void*)src);
    }
    cpa_commit();
}

// MODE 0: fp32 row-major out. MODE 1: Q bf16 split scaled [b,h,s,dh].
// MODE 2: K bf16 split [b,h,s,dh]. MODE 3: V bf16 split transposed [b,h,dh,s].
template <int MODE>
__global__ __launch_bounds__(256, 2)
void gemm_tc_kernel(const __nv_bfloat16* __restrict__ Ah, const __nv_bfloat16* __restrict__ Al,
                    const __nv_bfloat16* __restrict__ Bh, const __nv_bfloat16* __restrict__ Bl,
                    const float* __restrict__ bias, float* __restrict__ Y,
                    __nv_bfloat16* __restrict__ Yh, __nv_bfloat16* __restrict__ Yl) {
    extern __shared__ char dsm[];
    const int tid = threadIdx.x;
    const int lane = tid & 31;
    const int wid = tid >> 5;
    const int mwarp = wid & 3;
    const int nwarp = wid >> 2;
    const int n0 = blockIdx.x * BN;
    const int m0 = blockIdx.y * BM;

    const uint32_t sbase = smem_u32(dsm);
    const int lr = lane & 7;
    const int lg = lane >> 3;

    float acc[2][8][4];
#pragma unroll
    for (int mt = 0; mt < 2; mt++)
#pragma unroll
        for (int nt = 0; nt < 8; nt++)
#pragma unroll
            for (int r = 0; r < 4; r++) acc[mt][nt][r] = 0.0f;

    load_stage(sbase, Ah, Al, Bh, Bl, m0, n0, 0, tid);
    load_stage(sbase + STG_B, Ah, Al, Bh, Bl, m0, n0, 1, tid);

    for (int c = 0; c < NCH; c++) {
        if (c < NCH - 1) asm volatile("cp.async.wait_group 1;" ::: "memory");
        else             asm volatile("cp.async.wait_group 0;" ::: "memory");
        __syncthreads();

        const uint32_t sb = sbase + (uint32_t)(c & 1) * STG_B;
        const uint32_t sAh = sb;
        const uint32_t sAl = sb + MAT_B;
        const uint32_t sBh = sb + 2 * MAT_B;
        const uint32_t sBl = sb + 3 * MAT_B;

#pragma unroll
        for (int ks = 0; ks < 2; ks++) {
            const int c0 = ks * 2;
            uint32_t ah[2][4], al[2][4];
#pragma unroll
            for (int mt = 0; mt < 2; mt++) {
                int row = mwarp * 32 + mt * 16 + lr + (lg & 1) * 8;
                int ch = c0 + (lg >> 1);
                uint32_t off = soff(row, ch);
                ldsm_x4(ah[mt][0], ah[mt][1], ah[mt][2], ah[mt][3], sAh + off);
                ldsm_x4(al[mt][0], al[mt][1], al[mt][2], al[mt][3], sAl + off);
            }
#pragma unroll
            for (int np = 0; np < 4; np++) {
                int brow = nwarp * 64 + np * 16 + lr + (lg >> 1) * 8;
                int bch = c0 + (lg & 1);
                uint32_t boff = soff(brow, bch);
                uint32_t bh0, bh1, bh2, bh3, bl0, bl1, bl2, bl3;
                ldsm_x4(bh0, bh1, bh2, bh3, sBh + boff);
                ldsm_x4(bl0, bl1, bl2, bl3, sBl + boff);
#pragma unroll
                for (int mt = 0; mt < 2; mt++) {
                    mma_bf16(acc[mt][2 * np + 0], ah[mt], bh0, bh1);
                    mma_bf16(acc[mt][2 * np + 1], ah[mt], bh2, bh3);
                    mma_bf16(acc[mt][2 * np + 0], ah[mt], bl0, bl1);
                    mma_bf16(acc[mt][2 * np + 1], ah[mt], bl2, bl3);
                    mma_bf16(acc[mt][2 * np + 0], al[mt], bh0, bh1);
                    mma_bf16(acc[mt][2 * np + 1], al[mt], bh2, bh3);
                }
            }
        }
        __syncthreads();
        if (c + 2 < NCH)
            load_stage(sb, Ah, Al, Bh, Bl, m0, n0, c + 2, tid);
    }

    // epilogue
#pragma unroll
    for (int mt = 0; mt < 2; mt++) {
#pragma unroll
        for (int half = 0; half < 2; half++) {
            int gm = m0 + mwarp * 32 + mt * 16 + (lane >> 2) + half * 8;
            int bidx = gm >> 11;
            int sidx = gm & (SS - 1);
#pragma unroll
            for (int nt = 0; nt < 8; nt++) {
                int ncol = n0 + nwarp * 64 + nt * 8 + 2 * (lane & 3);
                float2 bv = *reinterpret_cast<const float2*>(&bias[ncol]);
                float ox = acc[mt][nt][2 * half + 0] + bv.x;
                float oy = acc[mt][nt][2 * half + 1] + bv.y;
                if (MODE == 0) {
                    float2 o = {ox, oy};
                    *reinterpret_cast<float2*>(&Y[(size_t)gm * DD + ncol]) = o;
                } else {
                    if (MODE == 1) { ox *= 0.125f; oy *= 0.125f; }
                    uint32_t hq, lq;
                    split2(ox, oy, hq, lq);
                    int hh = ncol >> 6;
                    int dh = ncol & (DHD - 1);
                    if (MODE == 3) {
                        size_t base = (((size_t)bidx * HN + hh) * DHD + dh) * SS + sidx;
                        __nv_bfloat162 hv = *reinterpret_cast<__nv_bfloat162*>(&hq);
                        __nv_bfloat162 lv = *reinterpret_cast<__nv_bfloat162*>(&lq);
                        Yh[base] = hv.x; Yh[base + SS] = hv.y;
                        Yl[base] = lv.x; Yl[base + SS] = lv.y;
                    } else {
                        size_t base = (((size_t)bidx * HN + hh) * SS + sidx) * DHD + dh;
                        *reinterpret_cast<uint32_t*>(&Yh[base]) = hq;
                        *reinterpret_cast<uint32_t*>(&Yl[base]) = lq;
                    }
                }
            }
        }
    }
}

// ---------------------- tensor-core flash attention -------------------------
// CTA: 128 q rows x one (b,h). 8 warps, each m16. 64-key tiles, 2-stage pipe.
#define AQ_B 16384                 // one Q matrix (128 rows x 128B)
#define AT_B 8192                  // one K/VT matrix (64 rows x 128B)
#define ASTG_B (4 * AT_B)          // stage: Kh, Kl, VTh, VTl
#define ATT_SMEM (2 * AQ_B + 2 * ASTG_B)  // 98304

__device__ __forceinline__ uint32_t aoff(int r, int c) {  // 128B rows, 8 chunks
    return (uint32_t)(r * 128 + ((c ^ (r & 7)) << 4));
}

__device__ __forceinline__ void att_load_kv(uint32_t sb, size_t hb, int s0, int tid) {
#pragma unroll
    for (int t = 0; t < 8; t++) {
        int slot = t * 256 + tid;       // 0..2047
        int mat = slot >> 9;            // 0..3
        int i = slot & 511;
        int r = i >> 3;                 // 0..63
        int c = i & 7;
        uint32_t d = sb + mat * AT_B + aoff(r, c);
        const __nv_bfloat16* src;
        if (mat == 0)      src = g_kh + hb + (size_t)(s0 + r) * DHD + c * 8;
        else if (mat == 1) src = g_kl + hb + (size_t)(s0 + r) * DHD + c * 8;
        else if (mat == 2) src = g_vth + hb + (size_t)r * SS + s0 + c * 8;
        else               src = g_vtl + hb + (size_t)r * SS + s0 + c * 8;
        cpa16(d, (const void*)src);
    }
}

__global__ __launch_bounds__(256, 2)
void attn_kernel() {
    extern __shared__ char asm_[];
    const uint32_t sbase = smem_u32(asm_);
    const int tid = threadIdx.x;
    const int lane = tid & 31;
    const int wid = tid >> 5;
    const int lr = lane & 7;
    const int lg = lane >> 3;
    const int g = lane >> 2;
    const int t4 = lane & 3;

    const int Qi = 15 - blockIdx.x;       // long CTAs first
    const int h = blockIdx.y;
    const int b = blockIdx.z;
    const int q0 = Qi * 128;
    const size_t hb = ((size_t)b * HN + h) * SS * DHD;
    const int ntiles = 2 * Qi + 2;

    // prologue: Q (both mats) + stage0 in group 0; stage1 in group 1
    {
#pragma unroll
        for (int t = 0; t < 8; t++) {
            int slot = t * 256 + tid;    // 0..2047
            int mat = slot >> 10;        // 0..1
            int i = slot & 1023;
            int r = i >> 3;              // 0..127
            int c = i & 7;
            const __nv_bfloat16* src = (mat ? g_ql : g_qh) + hb + (size_t)(q0 + r) * DHD + c * 8;
            cpa16(sbase + mat * AQ_B + aoff(r, c), (const void*)src);
        }
        att_load_kv(sbase + 2 * AQ_B, hb, 0, tid);
        cpa_commit();
        att_load_kv(sbase + 2 * AQ_B + ASTG_B, hb, 64, tid);
        cpa_commit();
    }

    float S[8][4];
    float ctx[8][4];
    float mrow[2] = {-INFINITY, -INFINITY};
    float lrow[2] = {0.0f, 0.0f};
#pragma unroll
    for (int t = 0; t < 8; t++)
#pragma unroll
        for (int r = 0; r < 4; r++) ctx[t][r] = 0.0f;

    const int myrow = q0 + 16 * wid + g;

    for (int kt = 0; kt < ntiles; kt++) {
        const uint32_t stb = sbase + 2 * AQ_B + (uint32_t)(kt & 1) * ASTG_B;
        if (kt + 1 < ntiles) asm volatile("cp.async.wait_group 1;" ::: "memory");
        else                 asm volatile("cp.async.wait_group 0;" ::: "memory");
        __syncthreads();

        // ---- S = Qh·Kh + Qh·Kl + Ql·Kh ----
#pragma unroll
        for (int t = 0; t < 8; t++)
#pragma unroll
            for (int r = 0; r < 4; r++) S[t][r] = 0.0f;

#pragma unroll
        for (int k16 = 0; k16 < 4; k16++) {
            uint32_t qh4[4], ql4[4];
            uint32_t qo = aoff(16 * wid + lr + (lg & 1) * 8, 2 * k16 + (lg >> 1));
            ldsm_x4(qh4[0], qh4[1], qh4[2], qh4[3], sbase + qo);
            ldsm_x4(ql4[0], ql4[1], ql4[2], ql4[3], sbase + AQ_B + qo);
#pragma unroll
            for (int np = 0; np < 4; np++) {
                uint32_t ko = aoff(16 * np + lr + (lg >> 1) * 8, 2 * k16 + (lg & 1));
                uint32_t kh0, kh1, kh2, kh3, kl0, kl1, kl2, kl3;
                ldsm_x4(kh0, kh1, kh2, kh3, stb + ko);
                ldsm_x4(kl0, kl1, kl2, kl3, stb + AT_B + ko);
                mma_bf16(S[2 * np + 0], qh4, kh0, kh1);
                mma_bf16(S[2 * np + 1], qh4, kh2, kh3);
                mma_bf16(S[2 * np + 0], qh4, kl0, kl1);
                mma_bf16(S[2 * np + 1], qh4, kl2, kl3);
                mma_bf16(S[2 * np + 0], ql4, kh0, kh1);
                mma_bf16(S[2 * np + 1], ql4, kh2, kh3);
            }
        }

        // ---- causal mask (only last two tiles) ----
        const int kb = kt * 64;
        if (kt >= 2 * Qi) {
#pragma unroll
            for (int j = 0; j < 8; j++) {
#pragma unroll
                for (int cc = 0; cc < 2; cc++) {
                    int key = kb + 8 * j + 2 * t4 + cc;
                    if (key > myrow)     S[j][cc]     = -INFINITY;
                    if (key > myrow + 8) S[j][2 + cc] = -INFINITY;
                }
            }
        }

        // ---- online softmax ----
#pragma unroll
        for (int r = 0; r < 2; r++) {
            float mx = S[0][2 * r];
#pragma unroll
            for (int j = 0; j < 8; j++) {
                mx = fmaxf(mx, S[j][2 * r]);
                mx = fmaxf(mx, S[j][2 * r + 1]);
            }
            mx = fmaxf(mx, __shfl_xor_sync(0xffffffffu, mx, 1));
            mx = fmaxf(mx, __shfl_xor_sync(0xffffffffu, mx, 2));
            float mn = fmaxf(mrow[r], mx);
            float alpha = __expf(mrow[r] - mn);
            float rs = 0.0f;
#pragma unroll
            for (int j = 0; j < 8; j++) {
                float p0 = __expf(S[j][2 * r] - mn);
                float p1 = __expf(S[j][2 * r + 1] - mn);
                S[j][2 * r] = p0;
                S[j][2 * r + 1] = p1;
                rs += p0 + p1;
            }
            rs += __shfl_xor_sync(0xffffffffu, rs, 1);
            rs += __shfl_xor_sync(0xffffffffu, rs, 2);
            lrow[r] = lrow[r] * alpha + rs;
            mrow[r] = mn;
#pragma unroll
            for (int t = 0; t < 8; t++) {
                ctx[t][2 * r] *= alpha;
                ctx[t][2 * r + 1] *= alpha;
            }
        }

        // ---- ctx += Ph·Vh + Ph·Vl + Pl·Vh ----
#pragma unroll
        for (int j2 = 0; j2 < 4; j2++) {
            uint32_t ph[4], pl[4];
            split2(S[2 * j2][0],     S[2 * j2][1],     ph[0], pl[0]);
            split2(S[2 * j2][2],     S[2 * j2][3],     ph[1], pl[1]);
            split2(S[2 * j2 + 1][0], S[2 * j2 + 1][1], ph[2], pl[2]);
            split2(S[2 * j2 + 1][2], S[2 * j2 + 1][3], ph[3], pl[3]);
#pragma unroll
            for (int np = 0; np < 4; np++) {
                uint32_t vo = aoff(16 * np + lr + (lg >> 1) * 8, 2 * j2 + (lg & 1));
                uint32_t vh0, vh1, vh2, vh3, vl0, vl1, vl2, vl3;
                ldsm_x4(vh0, vh1, vh2, vh3, stb + 2 * AT_B + vo);
                ldsm_x4(vl0, vl1, vl2, vl3, stb + 3 * AT_B + vo);
                mma_bf16(ctx[2 * np + 0], ph, vh0, vh1);
                mma_bf16(ctx[2 * np + 1], ph, vh2, vh3);
                mma_bf16(ctx[2 * np + 0], ph, vl0, vl1);
                mma_bf16(ctx[2 * np + 1], ph, vl2, vl3);
                mma_bf16(ctx[2 * np + 0], pl, vh0, vh1);
                mma_bf16(ctx[2 * np + 1], pl, vh2, vh3);
            }
        }

        __syncthreads();
        if (kt + 2 < ntiles) {
            att_load_kv(stb, hb, (kt + 2) * 64, tid);
            cpa_commit();
        }
    }

    // ---- epilogue: normalize, split, store ctx ----
#pragma unroll
    for (int r = 0; r < 2; r++) {
        float inv = 1.0f / lrow[r];
        int srow = q0 + 16 * wid + g + 8 * r;
        size_t base = ((size_t)b * SS + srow) * DD + h * DHD;
#pragma unroll
        for (int t = 0; t < 8; t++) {
            uint32_t hq, lq;
            split2(ctx[t][2 * r] * inv, ctx[t][2 * r + 1] * inv, hq, lq);
            size_t idx = base + 8 * t + 2 * t4;
            *reinterpret_cast<uint32_t*>(&g_ch[idx]) = hq;
            *reinterpret_cast<uint32_t*>(&g_cl[idx]) = lq;
        }
    }
}

// ---------------------------------------------------------------------------
extern "C" void kernel_launch(void* const* d_in, const int* in_sizes, int n_in,
                              void* d_out, int out_size) {
    const float* x  = (const float*)d_in[0];
    const float* Wq = (const float*)d_in[1];
    const float* bq = (const float*)d_in[2];
    const float* Wk = (const float*)d_in[3];
    const float* bk = (const float*)d_in[4];
    const float* Wv = (const float*)d_in[5];
    const float* bv = (const float*)d_in[6];
    const float* Wo = (const float*)d_in[7];
    const float* bo = (const float*)d_in[8];
    float* out = (float*)d_out;

    __nv_bfloat16 *pxh, *pxl, *pwht, *pwlt, *pch, *pcl;
    __nv_bfloat16 *pqh, *pql, *pkh, *pkl, *pvth, *pvtl;
    cudaGetSymbolAddress((void**)&pxh, g_xh);
    cudaGetSymbolAddress((void**)&pxl, g_xl);
    cudaGetSymbolAddress((void**)&pwht, g_wht);
    cudaGetSymbolAddress((void**)&pwlt, g_wlt);
    cudaGetSymbolAddress((void**)&pqh, g_qh);
    cudaGetSymbolAddress((void**)&pql, g_ql);
    cudaGetSymbolAddress((void**)&pkh, g_kh);
    cudaGetSymbolAddress((void**)&pkl, g_kl);
    cudaGetSymbolAddress((void**)&pvth, g_vth);
    cudaGetSymbolAddress((void**)&pvtl, g_vtl);
    cudaGetSymbolAddress((void**)&pch, g_ch);
    cudaGetSymbolAddress((void**)&pcl, g_cl);

    cudaFuncSetAttribute(gemm_tc_kernel<0>, cudaFuncAttributeMaxDynamicSharedMemorySize, GEMM_SMEM);
    cudaFuncSetAttribute(gemm_tc_kernel<1>, cudaFuncAttributeMaxDynamicSharedMemorySize, GEMM_SMEM);
    cudaFuncSetAttribute(gemm_tc_kernel<2>, cudaFuncAttributeMaxDynamicSharedMemorySize, GEMM_SMEM);
    cudaFuncSetAttribute(gemm_tc_kernel<3>, cudaFuncAttributeMaxDynamicSharedMemorySize, GEMM_SMEM);
    cudaFuncSetAttribute(attn_kernel, cudaFuncAttributeMaxDynamicSharedMemorySize, ATT_SMEM);

    convert_x_kernel<<<(MROWS * DD / 4) / 256, 256>>>(x, pxh, pxl);

    dim3 tgrid(DD / 32, DD / 32);
    convert_wT_kernel<<<tgrid, 256>>>(Wq, pwht + 0 * DD * DD, pwlt + 0 * DD * DD);
    convert_wT_kernel<<<tgrid, 256>>>(Wk, pwht + 1 * DD * DD, pwlt + 1 * DD * DD);
    convert_wT_kernel<<<tgrid, 256>>>(Wv, pwht + 2 * DD * DD, pwlt + 2 * DD * DD);
    convert_wT_kernel<<<tgrid, 256>>>(Wo, pwht + 3 * DD * DD, pwlt + 3 * DD * DD);

    dim3 ggrid(DD / BN, MROWS / BM);  // (8, 32)
    gemm_tc_kernel<1><<<ggrid, 256, GEMM_SMEM>>>(pxh, pxl, pwht + 0 * DD * DD, pwlt + 0 * DD * DD, bq, nullptr, pqh, pql);
    gemm_tc_kernel<2><<<ggrid, 256, GEMM_SMEM>>>(pxh, pxl, pwht + 1 * DD * DD, pwlt + 1 * DD * DD, bk, nullptr, pkh, pkl);
    gemm_tc_kernel<3><<<ggrid, 256, GEMM_SMEM>>>(pxh, pxl, pwht + 2 * DD * DD, pwlt + 2 * DD * DD, bv, nullptr, pvth, pvtl);

    dim3 agrid(SS / 128, HN, BB);  // (16, 16, 2)
    attn_kernel<<<agrid, 256, ATT_SMEM>>>();

    gemm_tc_kernel<0><<<ggrid, 256, GEMM_SMEM>>>(pch, pcl, pwht + 3 * DD * DD, pwlt + 3 * DD * DD, bo, out, nullptr, nullptr);
}

// round 5
// speedup vs baseline: 3.6884x; 1.0284x over previous
#include <cuda_runtime.h>
#include <cuda_bf16.h>
#include <math.h>
#include <stdint.h>

#define HN 16
#define DHD 64
#define DD 1024
#define BB 2
#define SS 2048
#define MROWS (BB * SS)   // 4096

// ------------------------- device scratch (no allocs) -----------------------
__device__ __align__(16) __nv_bfloat16 g_xh[MROWS * DD];
__device__ __align__(16) __nv_bfloat16 g_xl[MROWS * DD];
__device__ __align__(16) __nv_bfloat16 g_wht[4][DD * DD];  // [N][K] hi
__device__ __align__(16) __nv_bfloat16 g_wlt[4][DD * DD];  // [N][K] lo
// Q/K: [b,h,s,dh] bf16 hi/lo (Q pre-scaled by 0.125); V transposed: [b,h,dh,s]
__device__ __align__(16) __nv_bfloat16 g_qh[BB * HN * SS * DHD];
__device__ __align__(16) __nv_bfloat16 g_ql[BB * HN * SS * DHD];
__device__ __align__(16) __nv_bfloat16 g_kh[BB * HN * SS * DHD];
__device__ __align__(16) __nv_bfloat16 g_kl[BB * HN * SS * DHD];
__device__ __align__(16) __nv_bfloat16 g_vth[BB * HN * SS * DHD];
__device__ __align__(16) __nv_bfloat16 g_vtl[BB * HN * SS * DHD];
__device__ __align__(16) __nv_bfloat16 g_ch[MROWS * DD];
__device__ __align__(16) __nv_bfloat16 g_cl[MROWS * DD];

// ------------------------------ ptx helpers --------------------------------
__device__ __forceinline__ uint32_t smem_u32(const void* p) {
    return (uint32_t)__cvta_generic_to_shared(p);
}
__device__ __forceinline__ void cpa16(uint32_t d, const void* s) {
    asm volatile("cp.async.cg.shared.global [%0], [%1], 16;" :: "r"(d), "l"(s));
}
__device__ __forceinline__ void cpa_commit() {
    asm volatile("cp.async.commit_group;" ::: "memory");
}
__device__ __forceinline__ void ldsm_x4(uint32_t& d0, uint32_t& d1, uint32_t& d2,
                                        uint32_t& d3, uint32_t addr) {
    asm volatile("ldmatrix.sync.aligned.m8n8.x4.shared.b16 {%0,%1,%2,%3}, [%4];"
                 : "=r"(d0), "=r"(d1), "=r"(d2), "=r"(d3) : "r"(addr));
}
__device__ __forceinline__ void mma_bf16(float* c, const uint32_t* a,
                                         uint32_t b0, uint32_t b1) {
    asm volatile(
        "mma.sync.aligned.m16n8k16.row.col.f32.bf16.bf16.f32 "
        "{%0,%1,%2,%3}, {%4,%5,%6,%7}, {%8,%9}, {%0,%1,%2,%3};"
        : "+f"(c[0]), "+f"(c[1]), "+f"(c[2]), "+f"(c[3])
        : "r"(a[0]), "r"(a[1]), "r"(a[2]), "r"(a[3]), "r"(b0), "r"(b1));
}
__device__ __forceinline__ void split2(float x, float y, uint32_t& h, uint32_t& l) {
    __nv_bfloat162 bh = __floats2bfloat162_rn(x, y);
    __nv_bfloat162 bl = __floats2bfloat162_rn(x - __bfloat162float(bh.x),
                                              y - __bfloat162float(bh.y));
    h = *reinterpret_cast<uint32_t*>(&bh);
    l = *reinterpret_cast<uint32_t*>(&bl);
}

// ---------------------------- conversion kernels ---------------------------
__global__ __launch_bounds__(256)
void convert_x_kernel(const float* __restrict__ X,
                      __nv_bfloat16* __restrict__ Xh,
                      __nv_bfloat16* __restrict__ Xl) {
    size_t i = (size_t)blockIdx.x * blockDim.x + threadIdx.x;
    float4 v = reinterpret_cast<const float4*>(X)[i];
    uint32_t h0, l0, h1, l1;
    split2(v.x, v.y, h0, l0);
    split2(v.z, v.w, h1, l1);
    reinterpret_cast<uint32_t*>(Xh)[2 * i + 0] = h0;
    reinterpret_cast<uint32_t*>(Xh)[2 * i + 1] = h1;
    reinterpret_cast<uint32_t*>(Xl)[2 * i + 0] = l0;
    reinterpret_cast<uint32_t*>(Xl)[2 * i + 1] = l1;
}

// All 4 weights in one launch (grid.z selects weight)
__global__ __launch_bounds__(256)
void convert_wT_kernel(const float* __restrict__ W0, const float* __restrict__ W1,
                       const float* __restrict__ W2, const float* __restrict__ W3) {
    __shared__ float t[32][33];
    const int w = blockIdx.z;
    const float* W = (w == 0) ? W0 : (w == 1) ? W1 : (w == 2) ? W2 : W3;
    __nv_bfloat16* WhT = g_wht[w];
    __nv_bfloat16* WlT = g_wlt[w];
    int n0 = blockIdx.x * 32, k0 = blockIdx.y * 32;
    int tx = threadIdx.x & 31;
    int ty = threadIdx.x >> 5;
#pragma unroll
    for (int j = 0; j < 4; j++)
        t[ty + 8 * j][tx] = W[(size_t)(k0 + ty + 8 * j) * DD + n0 + tx];
    __syncthreads();
#pragma unroll
    for (int j = 0; j < 4; j++) {
        float v = t[tx][ty + 8 * j];
        __nv_bfloat16 h = __float2bfloat16(v);
        size_t o = (size_t)(n0 + ty + 8 * j) * DD + k0 + tx;
        WhT[o] = h;
        WlT[o] = __float2bfloat16(v - __bfloat162float(h));
    }
}

// ------------------------- mma.sync bf16x3 GEMM -----------------------------
#define BM 128
#define BN 128
#define BK 32
#define NCH (DD / BK)       // 32
#define MAT_B (BM * BK * 2)
#define STG_B (4 * MAT_B)   // 32768
#define NSTG 3
#define GEMM_SMEM (NSTG * STG_B)  // 98304

__device__ __forceinline__ uint32_t soff(int r, int c) {
    return (uint32_t)(r * 64 + ((c ^ ((r >> 1) & 3)) << 4));
}

__device__ __forceinline__ void load_stage(uint32_t sb,
                                           const __nv_bfloat16* Ah, const __nv_bfloat16* Al,
                                           const __nv_bfloat16* Bh, const __nv_bfloat16* Bl,
                                           int m0, int n0, int chunk, int tid) {
    const int kb = chunk * BK;
#pragma unroll
    for (int t = 0; t < 8; t++) {
        int idx = t * 256 + tid;
        int mat = idx >> 9;
        int i = idx & 511;
        int r = i >> 2;
        int c = i & 3;
        uint32_t d = sb + mat * MAT_B + soff(r, c);
        const __nv_bfloat16* src;
        if (mat == 0)      src = Ah + (size_t)(m0 + r) * DD + kb + c * 8;
        else if (mat == 1) src = Al + (size_t)(m0 + r) * DD + kb + c * 8;
        else if (mat == 2) src = Bh + (size_t)(n0 + r) * DD + kb + c * 8;
        else               src = Bl + (size_t)(n0 + r) * DD + kb + c * 8;
        cpa16(d, (const void*)src);
    }
    cpa_commit();
}

// QKV=1: grid.z selects proj (0=Q scaled [b,h,s,dh], 1=K [b,h,s,dh], 2=V trans [b,h,dh,s])
// QKV=0: fp32 row-major output with bias0.
template <int QKV>
__global__ __launch_bounds__(256, 2)
void gemm_tc_kernel(const __nv_bfloat16* __restrict__ Ah, const __nv_bfloat16* __restrict__ Al,
                    const float* __restrict__ b0, const float* __restrict__ b1,
                    const float* __restrict__ b2, float* __restrict__ Y) {
    extern __shared__ char dsm[];
    const int tid = threadIdx.x;
    const int lane = tid & 31;
    const int wid = tid >> 5;
    const int mwarp = wid & 3;
    const int nwarp = wid >> 2;
    const int n0 = blockIdx.x * BN;
    const int m0 = blockIdx.y * BM;
    const int proj = QKV ? blockIdx.z : 3;

    const __nv_bfloat16* Bh = g_wht[proj];
    const __nv_bfloat16* Bl = g_wlt[proj];
    const float* bias = QKV ? ((proj == 0) ? b0 : (proj == 1) ? b1 : b2) : b0;

    const uint32_t sbase = smem_u32(dsm);
    const int lr = lane & 7;
    const int lg = lane >> 3;

    float acc[2][8][4];
#pragma unroll
    for (int mt = 0; mt < 2; mt++)
#pragma unroll
        for (int nt = 0; nt < 8; nt++)
#pragma unroll
            for (int r = 0; r < 4; r++) acc[mt][nt][r] = 0.0f;

    load_stage(sbase, Ah, Al, Bh, Bl, m0, n0, 0, tid);
    load_stage(sbase + STG_B, Ah, Al, Bh, Bl, m0, n0, 1, tid);

    int slot_c = 0;   // slot of chunk c
    int slot_n = 2;   // slot for chunk c+2
    for (int c = 0; c < NCH; c++) {
        if (c < NCH - 1) asm volatile("cp.async.wait_group 1;" ::: "memory");
        else             asm volatile("cp.async.wait_group 0;" ::: "memory");
        __syncthreads();
        if (c + 2 < NCH)
            load_stage(sbase + (uint32_t)slot_n * STG_B, Ah, Al, Bh, Bl, m0, n0, c + 2, tid);

        const uint32_t sb = sbase + (uint32_t)slot_c * STG_B;
        const uint32_t sAh = sb;
        const uint32_t sAl = sb + MAT_B;
        const uint32_t sBh = sb + 2 * MAT_B;
        const uint32_t sBl = sb + 3 * MAT_B;

#pragma unroll
        for (int ks = 0; ks < 2; ks++) {
            const int c0 = ks * 2;
            uint32_t ah[2][4], al[2][4];
#pragma unroll
            for (int mt = 0; mt < 2; mt++) {
                int row = mwarp * 32 + mt * 16 + lr + (lg & 1) * 8;
                int ch = c0 + (lg >> 1);
                uint32_t off = soff(row, ch);
                ldsm_x4(ah[mt][0], ah[mt][1], ah[mt][2], ah[mt][3], sAh + off);
                ldsm_x4(al[mt][0], al[mt][1], al[mt][2], al[mt][3], sAl + off);
            }
#pragma unroll
            for (int np = 0; np < 4; np++) {
                int brow = nwarp * 64 + np * 16 + lr + (lg >> 1) * 8;
                int bch = c0 + (lg & 1);
                uint32_t boff = soff(brow, bch);
                uint32_t bh0, bh1, bh2, bh3, bl0, bl1, bl2, bl3;
                ldsm_x4(bh0, bh1, bh2, bh3, sBh + boff);
                ldsm_x4(bl0, bl1, bl2, bl3, sBl + boff);
#pragma unroll
                for (int mt = 0; mt < 2; mt++) {
                    mma_bf16(acc[mt][2 * np + 0], ah[mt], bh0, bh1);
                    mma_bf16(acc[mt][2 * np + 1], ah[mt], bh2, bh3);
                    mma_bf16(acc[mt][2 * np + 0], ah[mt], bl0, bl1);
                    mma_bf16(acc[mt][2 * np + 1], ah[mt], bl2, bl3);
                    mma_bf16(acc[mt][2 * np + 0], al[mt], bh0, bh1);
                    mma_bf16(acc[mt][2 * np + 1], al[mt], bh2, bh3);
                }
            }
        }
        slot_c = (slot_c == NSTG - 1) ? 0 : slot_c + 1;
        slot_n = (slot_n == NSTG - 1) ? 0 : slot_n + 1;
    }

    // epilogue
    __nv_bfloat16* Yh;
    __nv_bfloat16* Yl;
    if (QKV) {
        Yh = (proj == 0) ? g_qh : (proj == 1) ? g_kh : g_vth;
        Yl = (proj == 0) ? g_ql : (proj == 1) ? g_kl : g_vtl;
    }
#pragma unroll
    for (int mt = 0; mt < 2; mt++) {
#pragma unroll
        for (int half = 0; half < 2; half++) {
            int gm = m0 + mwarp * 32 + mt * 16 + (lane >> 2) + half * 8;
            int bidx = gm >> 11;
            int sidx = gm & (SS - 1);
#pragma unroll
            for (int nt = 0; nt < 8; nt++) {
                int ncol = n0 + nwarp * 64 + nt * 8 + 2 * (lane & 3);
                float2 bv = *reinterpret_cast<const float2*>(&bias[ncol]);
                float ox = acc[mt][nt][2 * half + 0] + bv.x;
                float oy = acc[mt][nt][2 * half + 1] + bv.y;
                if (!QKV) {
                    float2 o = {ox, oy};
                    *reinterpret_cast<float2*>(&Y[(size_t)gm * DD + ncol]) = o;
                } else {
                    if (proj == 0) { ox *= 0.125f; oy *= 0.125f; }
                    uint32_t hq, lq;
                    split2(ox, oy, hq, lq);
                    int hh = ncol >> 6;
                    int dh = ncol & (DHD - 1);
                    if (proj == 2) {
                        size_t base = (((size_t)bidx * HN + hh) * DHD + dh) * SS + sidx;
                        __nv_bfloat162 hv = *reinterpret_cast<__nv_bfloat162*>(&hq);
                        __nv_bfloat162 lv = *reinterpret_cast<__nv_bfloat162*>(&lq);
                        Yh[base] = hv.x; Yh[base + SS] = hv.y;
                        Yl[base] = lv.x; Yl[base + SS] = lv.y;
                    } else {
                        size_t base = (((size_t)bidx * HN + hh) * SS + sidx) * DHD + dh;
                        *reinterpret_cast<uint32_t*>(&Yh[base]) = hq;
                        *reinterpret_cast<uint32_t*>(&Yl[base]) = lq;
                    }
                }
            }
        }
    }
}

// ---------------------- tensor-core flash attention -------------------------
#define AQ_B 16384
#define AT_B 8192
#define ASTG_B (4 * AT_B)
#define ATT_SMEM (2 * AQ_B + 2 * ASTG_B)  // 98304

__device__ __forceinline__ uint32_t aoff(int r, int c) {
    return (uint32_t)(r * 128 + ((c ^ (r & 7)) << 4));
}

__device__ __forceinline__ void att_load_kv(uint32_t sb, size_t hb, int s0, int tid) {
#pragma unroll
    for (int t = 0; t < 8; t++) {
        int slot = t * 256 + tid;
        int mat = slot >> 9;
        int i = slot & 511;
        int r = i >> 3;
        int c = i & 7;
        uint32_t d = sb + mat * AT_B + aoff(r, c);
        const __nv_bfloat16* src;
        if (mat == 0)      src = g_kh + hb + (size_t)(s0 + r) * DHD + c * 8;
        else if (mat == 1) src = g_kl + hb + (size_t)(s0 + r) * DHD + c * 8;
        else if (mat == 2) src = g_vth + hb + (size_t)r * SS + s0 + c * 8;
        else               src = g_vtl + hb + (size_t)r * SS + s0 + c * 8;
        cpa16(d, (const void*)src);
    }
}

__global__ __launch_bounds__(256, 2)
void attn_kernel() {
    extern __shared__ char asm_[];
    const uint32_t sbase = smem_u32(asm_);
    const int tid = threadIdx.x;
    const int lane = tid & 31;
    const int wid = tid >> 5;
    const int lr = lane & 7;
    const int lg = lane >> 3;
    const int g = lane >> 2;
    const int t4 = lane & 3;

    const int Qi = 15 - blockIdx.x;
    const int h = blockIdx.y;
    const int b = blockIdx.z;
    const int q0 = Qi * 128;
    const size_t hb = ((size_t)b * HN + h) * SS * DHD;
    const int ntiles = 2 * Qi + 2;

    {
#pragma unroll
        for (int t = 0; t < 8; t++) {
            int slot = t * 256 + tid;
            int mat = slot >> 10;
            int i = slot & 1023;
            int r = i >> 3;
            int c = i & 7;
            const __nv_bfloat16* src = (mat ? g_ql : g_qh) + hb + (size_t)(q0 + r) * DHD + c * 8;
            cpa16(sbase + mat * AQ_B + aoff(r, c), (const void*)src);
        }
        att_load_kv(sbase + 2 * AQ_B, hb, 0, tid);
        cpa_commit();
        att_load_kv(sbase + 2 * AQ_B + ASTG_B, hb, 64, tid);
        cpa_commit();
    }

    float S[8][4];
    float ctx[8][4];
    uint32_t qfh[4][4];                      // hoisted Qh fragments
    float mrow[2] = {-INFINITY, -INFINITY};
    float lrow[2] = {0.0f, 0.0f};
#pragma unroll
    for (int t = 0; t < 8; t++)
#pragma unroll
        for (int r = 0; r < 4; r++) ctx[t][r] = 0.0f;

    const int myrow = q0 + 16 * wid + g;

    for (int kt = 0; kt < ntiles; kt++) {
        const uint32_t stb = sbase + 2 * AQ_B + (uint32_t)(kt & 1) * ASTG_B;
        if (kt + 1 < ntiles) asm volatile("cp.async.wait_group 1;" ::: "memory");
        else                 asm volatile("cp.async.wait_group 0;" ::: "memory");
        __syncthreads();

        if (kt == 0) {
#pragma unroll
            for (int k16 = 0; k16 < 4; k16++) {
                uint32_t qo = aoff(16 * wid + lr + (lg & 1) * 8, 2 * k16 + (lg >> 1));
                ldsm_x4(qfh[k16][0], qfh[k16][1], qfh[k16][2], qfh[k16][3], sbase + qo);
            }
        }

#pragma unroll
        for (int t = 0; t < 8; t++)
#pragma unroll
            for (int r = 0; r < 4; r++) S[t][r] = 0.0f;

#pragma unroll
        for (int k16 = 0; k16 < 4; k16++) {
            uint32_t ql4[4];
            uint32_t qo = aoff(16 * wid + lr + (lg & 1) * 8, 2 * k16 + (lg >> 1));
            ldsm_x4(ql4[0], ql4[1], ql4[2], ql4[3], sbase + AQ_B + qo);
#pragma unroll
            for (int np = 0; np < 4; np++) {
                uint32_t ko = aoff(16 * np + lr + (lg >> 1) * 8, 2 * k16 + (lg & 1));
                uint32_t kh0, kh1, kh2, kh3, kl0, kl1, kl2, kl3;
                ldsm_x4(kh0, kh1, kh2, kh3, stb + ko);
                ldsm_x4(kl0, kl1, kl2, kl3, stb + AT_B + ko);
                mma_bf16(S[2 * np + 0], qfh[k16], kh0, kh1);
                mma_bf16(S[2 * np + 1], qfh[k16], kh2, kh3);
                mma_bf16(S[2 * np + 0], qfh[k16], kl0, kl1);
                mma_bf16(S[2 * np + 1], qfh[k16], kl2, kl3);
                mma_bf16(S[2 * np + 0], ql4, kh0, kh1);
                mma_bf16(S[2 * np + 1], ql4, kh2, kh3);
            }
        }

        const int kb = kt * 64;
        if (kt >= 2 * Qi) {
#pragma unroll
            for (int j = 0; j < 8; j++) {
#pragma unroll
                for (int cc = 0; cc < 2; cc++) {
                    int key = kb + 8 * j + 2 * t4 + cc;
                    if (key > myrow)     S[j][cc]     = -INFINITY;
                    if (key > myrow + 8) S[j][2 + cc] = -INFINITY;
                }
            }
        }

#pragma unroll
        for (int r = 0; r < 2; r++) {
            float mx = S[0][2 * r];
#pragma unroll
            for (int j = 0; j < 8; j++) {
                mx = fmaxf(mx, S[j][2 * r]);
                mx = fmaxf(mx, S[j][2 * r + 1]);
            }
            mx = fmaxf(mx, __shfl_xor_sync(0xffffffffu, mx, 1));
            mx = fmaxf(mx, __shfl_xor_sync(0xffffffffu, mx, 2));
            float mn = fmaxf(mrow[r], mx);
            float alpha = __expf(mrow[r] - mn);
            float rs = 0.0f;
#pragma unroll
            for (int j = 0; j < 8; j++) {
                float p0 = __expf(S[j][2 * r] - mn);
                float p1 = __expf(S[j][2 * r + 1] - mn);
                S[j][2 * r] = p0;
                S[j][2 * r + 1] = p1;
                rs += p0 + p1;
            }
            rs += __shfl_xor_sync(0xffffffffu, rs, 1);
            rs += __shfl_xor_sync(0xffffffffu, rs, 2);
            lrow[r] = lrow[r] * alpha + rs;
            mrow[r] = mn;
#pragma unroll
            for (int t = 0; t < 8; t++) {
                ctx[t][2 * r] *= alpha;
                ctx[t][2 * r + 1] *= alpha;
            }
        }

#pragma unroll
        for (int j2 = 0; j2 < 4; j2++) {
            uint32_t ph[4], pl[4];
            split2(S[2 * j2][0],     S[2 * j2][1],     ph[0], pl[0]);
            split2(S[2 * j2][2],     S[2 * j2][3],     ph[1], pl[1]);
            split2(S[2 * j2 + 1][0], S[2 * j2 + 1][1], ph[2], pl[2]);
            split2(S[2 * j2 + 1][2], S[2 * j2 + 1][3], ph[3], pl[3]);
#pragma unroll
            for (int np = 0; np < 4; np++) {
                uint32_t vo = aoff(16 * np + lr + (lg >> 1) * 8, 2 * j2 + (lg & 1));
                uint32_t vh0, vh1, vh2, vh3, vl0, vl1, vl2, vl3;
                ldsm_x4(vh0, vh1, vh2, vh3, stb + 2 * AT_B + vo);
                ldsm_x4(vl0, vl1, vl2, vl3, stb + 3 * AT_B + vo);
                mma_bf16(ctx[2 * np + 0], ph, vh0, vh1);
                mma_bf16(ctx[2 * np + 1], ph, vh2, vh3);
                mma_bf16(ctx[2 * np + 0], ph, vl0, vl1);
                mma_bf16(ctx[2 * np + 1], ph, vl2, vl3);
                mma_bf16(ctx[2 * np + 0], pl, vh0, vh1);
                mma_bf16(ctx[2 * np + 1], pl, vh2, vh3);
            }
        }

        __syncthreads();
        if (kt + 2 < ntiles) {
            att_load_kv(stb, hb, (kt + 2) * 64, tid);
            cpa_commit();
        }
    }

#pragma unroll
    for (int r = 0; r < 2; r++) {
        float inv = 1.0f / lrow[r];
        int srow = q0 + 16 * wid + g + 8 * r;
        size_t base = ((size_t)b * SS + srow) * DD + h * DHD;
#pragma unroll
        for (int t = 0; t < 8; t++) {
            uint32_t hq, lq;
            split2(ctx[t][2 * r] * inv, ctx[t][2 * r + 1] * inv, hq, lq);
            size_t idx = base + 8 * t + 2 * t4;
            *reinterpret_cast<uint32_t*>(&g_ch[idx]) = hq;
            *reinterpret_cast<uint32_t*>(&g_cl[idx]) = lq;
        }
    }
}

// ---------------------------------------------------------------------------
extern "C" void kernel_launch(void* const* d_in, const int* in_sizes, int n_in,
                              void* d_out, int out_size) {
    const float* x  = (const float*)d_in[0];
    const float* Wq = (const float*)d_in[1];
    const float* bq = (const float*)d_in[2];
    const float* Wk = (const float*)d_in[3];
    const float* bk = (const float*)d_in[4];
    const float* Wv = (const float*)d_in[5];
    const float* bv = (const float*)d_in[6];
    const float* Wo = (const float*)d_in[7];
    const float* bo = (const float*)d_in[8];
    float* out = (float*)d_out;

    __nv_bfloat16 *pxh, *pxl, *pch, *pcl;
    cudaGetSymbolAddress((void**)&pxh, g_xh);
    cudaGetSymbolAddress((void**)&pxl, g_xl);
    cudaGetSymbolAddress((void**)&pch, g_ch);
    cudaGetSymbolAddress((void**)&pcl, g_cl);

    cudaFuncSetAttribute(gemm_tc_kernel<0>, cudaFuncAttributeMaxDynamicSharedMemorySize, GEMM_SMEM);
    cudaFuncSetAttribute(gemm_tc_kernel<1>, cudaFuncAttributeMaxDynamicSharedMemorySize, GEMM_SMEM);
    cudaFuncSetAttribute(attn_kernel, cudaFuncAttributeMaxDynamicSharedMemorySize, ATT_SMEM);

    convert_x_kernel<<<(MROWS * DD / 4) / 256, 256>>>(x, pxh, pxl);

    dim3 tgrid(DD / 32, DD / 32, 4);
    convert_wT_kernel<<<tgrid, 256>>>(Wq, Wk, Wv, Wo);

    // QKV fused (grid.z = proj)
    dim3 ggrid(DD / BN, MROWS / BM, 3);
    gemm_tc_kernel<1><<<ggrid, 256, GEMM_SMEM>>>(pxh, pxl, bq, bk, bv, nullptr);

    dim3 agrid(SS / 128, HN, BB);
    attn_kernel<<<agrid, 256, ATT_SMEM>>>();

    dim3 ogrid(DD / BN, MROWS / BM, 1);
    gemm_tc_kernel<0><<<ogrid, 256, GEMM_SMEM>>>(pch, pcl, bo, nullptr, nullptr, out);
}

// round 6
// speedup vs baseline: 5.1008x; 1.3829x over previous
#include <cuda_runtime.h>
#include <cuda_fp16.h>
#include <math.h>
#include <stdint.h>

#define HN 16
#define DHD 64
#define DD 1024
#define BB 2
#define SS 2048
#define MROWS (BB * SS)   // 4096

// ------------------------- device scratch (no allocs) -----------------------
__device__ __align__(16) __half g_xh[MROWS * DD];            // X fp16 (single)
__device__ __align__(16) __half g_wht[4][DD * DD];           // W^T hi [N][K]
__device__ __align__(16) __half g_wlt[4][DD * DD];           // W^T lo [N][K]
__device__ __align__(16) __half g_qh[BB * HN * SS * DHD];    // Q fp16, scaled 1/8
__device__ __align__(16) __half g_kh[BB * HN * SS * DHD];    // K hi
__device__ __align__(16) __half g_kl[BB * HN * SS * DHD];    // K lo
__device__ __align__(16) __half g_vth[BB * HN * SS * DHD];   // V^T hi [b,h,dh,s]
__device__ __align__(16) __half g_vtl[BB * HN * SS * DHD];   // V^T lo
__device__ __align__(16) __half g_ch[MROWS * DD];            // ctx fp16 (single)

// ------------------------------ ptx helpers --------------------------------
__device__ __forceinline__ uint32_t smem_u32(const void* p) {
    return (uint32_t)__cvta_generic_to_shared(p);
}
__device__ __forceinline__ void cpa16(uint32_t d, const void* s) {
    asm volatile("cp.async.cg.shared.global [%0], [%1], 16;" :: "r"(d), "l"(s));
}
__device__ __forceinline__ void cpa_commit() {
    asm volatile("cp.async.commit_group;" ::: "memory");
}
__device__ __forceinline__ void ldsm_x4(uint32_t& d0, uint32_t& d1, uint32_t& d2,
                                        uint32_t& d3, uint32_t addr) {
    asm volatile("ldmatrix.sync.aligned.m8n8.x4.shared.b16 {%0,%1,%2,%3}, [%4];"
                 : "=r"(d0), "=r"(d1), "=r"(d2), "=r"(d3) : "r"(addr));
}
__device__ __forceinline__ void mma_f16(float* c, const uint32_t* a,
                                        uint32_t b0, uint32_t b1) {
    asm volatile(
        "mma.sync.aligned.m16n8k16.row.col.f32.f16.f16.f32 "
        "{%0,%1,%2,%3}, {%4,%5,%6,%7}, {%8,%9}, {%0,%1,%2,%3};"
        : "+f"(c[0]), "+f"(c[1]), "+f"(c[2]), "+f"(c[3])
        : "r"(a[0]), "r"(a[1]), "r"(a[2]), "r"(a[3]), "r"(b0), "r"(b1));
}
__device__ __forceinline__ uint32_t h2pack(float x, float y) {
    __half2 t = __floats2half2_rn(x, y);
    return *reinterpret_cast<uint32_t*>(&t);
}
__device__ __forceinline__ void split2h(float x, float y, uint32_t& h, uint32_t& l) {
    __half2 hh = __floats2half2_rn(x, y);
    __half2 ll = __floats2half2_rn(x - __low2float(hh), y - __high2float(hh));
    h = *reinterpret_cast<uint32_t*>(&hh);
    l = *reinterpret_cast<uint32_t*>(&ll);
}

// ---------------------------- conversion kernels ---------------------------
__global__ __launch_bounds__(256)
void convert_x_kernel(const float* __restrict__ X, __half* __restrict__ Xh) {
    size_t i = (size_t)blockIdx.x * blockDim.x + threadIdx.x;
    float4 v = reinterpret_cast<const float4*>(X)[i];
    uint2 o;
    o.x = h2pack(v.x, v.y);
    o.y = h2pack(v.z, v.w);
    reinterpret_cast<uint2*>(Xh)[i] = o;
}

__global__ __launch_bounds__(256)
void convert_wT_kernel(const float* __restrict__ W0, const float* __restrict__ W1,
                       const float* __restrict__ W2, const float* __restrict__ W3) {
    __shared__ float t[32][33];
    const int w = blockIdx.z;
    const float* W = (w == 0) ? W0 : (w == 1) ? W1 : (w == 2) ? W2 : W3;
    __half* WhT = g_wht[w];
    __half* WlT = g_wlt[w];
    int n0 = blockIdx.x * 32, k0 = blockIdx.y * 32;
    int tx = threadIdx.x & 31;
    int ty = threadIdx.x >> 5;
#pragma unroll
    for (int j = 0; j < 4; j++)
        t[ty + 8 * j][tx] = W[(size_t)(k0 + ty + 8 * j) * DD + n0 + tx];
    __syncthreads();
#pragma unroll
    for (int j = 0; j < 4; j++) {
        float v = t[tx][ty + 8 * j];
        __half h = __float2half_rn(v);
        size_t o = (size_t)(n0 + ty + 8 * j) * DD + k0 + tx;
        WhT[o] = h;
        WlT[o] = __float2half_rn(v - __half2float(h));
    }
}

// ------------------------- mma.sync fp16 2-pass GEMM ------------------------
// Y[4096,1024] = Xh[M,K] @ (Wh+Wl)^T + bias
#define BM 128
#define BN 128
#define BK 32
#define NCH (DD / BK)       // 32
#define MAT_B (BM * BK * 2) // 8192
#define STG_B (3 * MAT_B)   // 24576 : A, Bh, Bl
#define NSTG 3
#define GEMM_SMEM (NSTG * STG_B)  // 73728

__device__ __forceinline__ uint32_t soff(int r, int c) {
    return (uint32_t)(r * 64 + ((c ^ ((r >> 1) & 3)) << 4));
}

__device__ __forceinline__ void load_stage(uint32_t sb,
                                           const __half* A,
                                           const __half* Bh, const __half* Bl,
                                           int m0, int n0, int chunk, int tid) {
    const int kb = chunk * BK;
#pragma unroll
    for (int t = 0; t < 6; t++) {
        int idx = t * 256 + tid;        // 0..1535
        int mat = idx >> 9;             // 0..2
        int i = idx & 511;
        int r = i >> 2;
        int c = i & 3;
        uint32_t d = sb + mat * MAT_B + soff(r, c);
        const __half* src;
        if (mat == 0)      src = A  + (size_t)(m0 + r) * DD + kb + c * 8;
        else if (mat == 1) src = Bh + (size_t)(n0 + r) * DD + kb + c * 8;
        else               src = Bl + (size_t)(n0 + r) * DD + kb + c * 8;
        cpa16(d, (const void*)src);
    }
    cpa_commit();
}

// QKV=1: grid.z = proj (0=Q scaled single, 1=K split, 2=V split transposed)
// QKV=0: fp32 row-major out + bias0.
template <int QKV>
__global__ __launch_bounds__(256, 2)
void gemm_tc_kernel(const __half* __restrict__ A,
                    const float* __restrict__ b0, const float* __restrict__ b1,
                    const float* __restrict__ b2, float* __restrict__ Y) {
    extern __shared__ char dsm[];
    const int tid = threadIdx.x;
    const int lane = tid & 31;
    const int wid = tid >> 5;
    const int mwarp = wid & 3;
    const int nwarp = wid >> 2;
    const int n0 = blockIdx.x * BN;
    const int m0 = blockIdx.y * BM;
    const int proj = QKV ? blockIdx.z : 3;

    const __half* Bh = g_wht[proj];
    const __half* Bl = g_wlt[proj];
    const float* bias = QKV ? ((proj == 0) ? b0 : (proj == 1) ? b1 : b2) : b0;

    const uint32_t sbase = smem_u32(dsm);
    const int lr = lane & 7;
    const int lg = lane >> 3;

    float acc[2][8][4];
#pragma unroll
    for (int mt = 0; mt < 2; mt++)
#pragma unroll
        for (int nt = 0; nt < 8; nt++)
#pragma unroll
            for (int r = 0; r < 4; r++) acc[mt][nt][r] = 0.0f;

    load_stage(sbase, A, Bh, Bl, m0, n0, 0, tid);
    load_stage(sbase + STG_B, A, Bh, Bl, m0, n0, 1, tid);

    int slot_c = 0;
    int slot_n = 2;
    for (int c = 0; c < NCH; c++) {
        if (c < NCH - 1) asm volatile("cp.async.wait_group 1;" ::: "memory");
        else             asm volatile("cp.async.wait_group 0;" ::: "memory");
        __syncthreads();
        if (c + 2 < NCH)
            load_stage(sbase + (uint32_t)slot_n * STG_B, A, Bh, Bl, m0, n0, c + 2, tid);

        const uint32_t sb = sbase + (uint32_t)slot_c * STG_B;
        const uint32_t sA  = sb;
        const uint32_t sBh = sb + MAT_B;
        const uint32_t sBl = sb + 2 * MAT_B;

#pragma unroll
        for (int ks = 0; ks < 2; ks++) {
            const int c0 = ks * 2;
            uint32_t av[2][4];
#pragma unroll
            for (int mt = 0; mt < 2; mt++) {
                int row = mwarp * 32 + mt * 16 + lr + (lg & 1) * 8;
                int ch = c0 + (lg >> 1);
                ldsm_x4(av[mt][0], av[mt][1], av[mt][2], av[mt][3], sA + soff(row, ch));
            }
#pragma unroll
            for (int np = 0; np < 4; np++) {
                int brow = nwarp * 64 + np * 16 + lr + (lg >> 1) * 8;
                int bch = c0 + (lg & 1);
                uint32_t boff = soff(brow, bch);
                uint32_t bh0, bh1, bh2, bh3, bl0, bl1, bl2, bl3;
                ldsm_x4(bh0, bh1, bh2, bh3, sBh + boff);
                ldsm_x4(bl0, bl1, bl2, bl3, sBl + boff);
#pragma unroll
                for (int mt = 0; mt < 2; mt++) {
                    mma_f16(acc[mt][2 * np + 0], av[mt], bh0, bh1);
                    mma_f16(acc[mt][2 * np + 1], av[mt], bh2, bh3);
                    mma_f16(acc[mt][2 * np + 0], av[mt], bl0, bl1);
                    mma_f16(acc[mt][2 * np + 1], av[mt], bl2, bl3);
                }
            }
        }
        slot_c = (slot_c == NSTG - 1) ? 0 : slot_c + 1;
        slot_n = (slot_n == NSTG - 1) ? 0 : slot_n + 1;
    }

    // epilogue
#pragma unroll
    for (int mt = 0; mt < 2; mt++) {
#pragma unroll
        for (int half = 0; half < 2; half++) {
            int gm = m0 + mwarp * 32 + mt * 16 + (lane >> 2) + half * 8;
            int bidx = gm >> 11;
            int sidx = gm & (SS - 1);
#pragma unroll
            for (int nt = 0; nt < 8; nt++) {
                int ncol = n0 + nwarp * 64 + nt * 8 + 2 * (lane & 3);
                float2 bv = *reinterpret_cast<const float2*>(&bias[ncol]);
                float ox = acc[mt][nt][2 * half + 0] + bv.x;
                float oy = acc[mt][nt][2 * half + 1] + bv.y;
                if (!QKV) {
                    float2 o = {ox, oy};
                    *reinterpret_cast<float2*>(&Y[(size_t)gm * DD + ncol]) = o;
                } else {
                    int hh = ncol >> 6;
                    int dh = ncol & (DHD - 1);
                    if (proj == 0) {
                        size_t base = (((size_t)bidx * HN + hh) * SS + sidx) * DHD + dh;
                        *reinterpret_cast<uint32_t*>(&g_qh[base]) =
                            h2pack(ox * 0.125f, oy * 0.125f);
                    } else if (proj == 1) {
                        uint32_t hq, lq;
                        split2h(ox, oy, hq, lq);
                        size_t base = (((size_t)bidx * HN + hh) * SS + sidx) * DHD + dh;
                        *reinterpret_cast<uint32_t*>(&g_kh[base]) = hq;
                        *reinterpret_cast<uint32_t*>(&g_kl[base]) = lq;
                    } else {
                        uint32_t hq, lq;
                        split2h(ox, oy, hq, lq);
                        size_t base = (((size_t)bidx * HN + hh) * DHD + dh) * SS + sidx;
                        __half2 hv = *reinterpret_cast<__half2*>(&hq);
                        __half2 lv = *reinterpret_cast<__half2*>(&lq);
                        g_vth[base] = __low2half(hv); g_vth[base + SS] = __high2half(hv);
                        g_vtl[base] = __low2half(lv); g_vtl[base + SS] = __high2half(lv);
                    }
                }
            }
        }
    }
}

// ---------------------- tensor-core flash attention (fp16) ------------------
#define AQ_B 16384                 // Q: 128 rows x 128B
#define AT_B 8192                  // K/V^T: 64 rows x 128B
#define ASTG_B (4 * AT_B)          // Kh, Kl, VTh, VTl
#define ATT_SMEM (AQ_B + 2 * ASTG_B)  // 81920

__device__ __forceinline__ uint32_t aoff(int r, int c) {
    return (uint32_t)(r * 128 + ((c ^ (r & 7)) << 4));
}

__device__ __forceinline__ void att_load_kv(uint32_t sb, size_t hb, int s0, int tid) {
#pragma unroll
    for (int t = 0; t < 8; t++) {
        int slot = t * 256 + tid;
        int mat = slot >> 9;
        int i = slot & 511;
        int r = i >> 3;
        int c = i & 7;
        uint32_t d = sb + mat * AT_B + aoff(r, c);
        const __half* src;
        if (mat == 0)      src = g_kh + hb + (size_t)(s0 + r) * DHD + c * 8;
        else if (mat == 1) src = g_kl + hb + (size_t)(s0 + r) * DHD + c * 8;
        else if (mat == 2) src = g_vth + hb + (size_t)r * SS + s0 + c * 8;
        else               src = g_vtl + hb + (size_t)r * SS + s0 + c * 8;
        cpa16(d, (const void*)src);
    }
}

__global__ __launch_bounds__(256, 2)
void attn_kernel() {
    extern __shared__ char asm_[];
    const uint32_t sbase = smem_u32(asm_);
    const int tid = threadIdx.x;
    const int lane = tid & 31;
    const int wid = tid >> 5;
    const int lr = lane & 7;
    const int lg = lane >> 3;
    const int g = lane >> 2;
    const int t4 = lane & 3;

    const int Qi = 15 - blockIdx.x;
    const int h = blockIdx.y;
    const int b = blockIdx.z;
    const int q0 = Qi * 128;
    const size_t hb = ((size_t)b * HN + h) * SS * DHD;
    const int ntiles = 2 * Qi + 2;

    {   // Q (single) + stage0; then stage1
#pragma unroll
        for (int t = 0; t < 4; t++) {
            int idx = t * 256 + tid;     // 0..1023
            int r = idx >> 3;
            int c = idx & 7;
            cpa16(sbase + aoff(r, c), (const void*)(g_qh + hb + (size_t)(q0 + r) * DHD + c * 8));
        }
        att_load_kv(sbase + AQ_B, hb, 0, tid);
        cpa_commit();
        att_load_kv(sbase + AQ_B + ASTG_B, hb, 64, tid);
        cpa_commit();
    }

    float S[8][4];
    float ctx[8][4];
    uint32_t qf[4][4];
    float mrow[2] = {-INFINITY, -INFINITY};
    float lrow[2] = {0.0f, 0.0f};
#pragma unroll
    for (int t = 0; t < 8; t++)
#pragma unroll
        for (int r = 0; r < 4; r++) ctx[t][r] = 0.0f;

    const int myrow = q0 + 16 * wid + g;

    for (int kt = 0; kt < ntiles; kt++) {
        const uint32_t stb = sbase + AQ_B + (uint32_t)(kt & 1) * ASTG_B;
        if (kt + 1 < ntiles) asm volatile("cp.async.wait_group 1;" ::: "memory");
        else                 asm volatile("cp.async.wait_group 0;" ::: "memory");
        __syncthreads();

        if (kt == 0) {
#pragma unroll
            for (int k16 = 0; k16 < 4; k16++) {
                uint32_t qo = aoff(16 * wid + lr + (lg & 1) * 8, 2 * k16 + (lg >> 1));
                ldsm_x4(qf[k16][0], qf[k16][1], qf[k16][2], qf[k16][3], sbase + qo);
            }
        }

#pragma unroll
        for (int t = 0; t < 8; t++)
#pragma unroll
            for (int r = 0; r < 4; r++) S[t][r] = 0.0f;

        // ---- S = Q·Kh + Q·Kl ----
#pragma unroll
        for (int k16 = 0; k16 < 4; k16++) {
#pragma unroll
            for (int np = 0; np < 4; np++) {
                uint32_t ko = aoff(16 * np + lr + (lg >> 1) * 8, 2 * k16 + (lg & 1));
                uint32_t kh0, kh1, kh2, kh3, kl0, kl1, kl2, kl3;
                ldsm_x4(kh0, kh1, kh2, kh3, stb + ko);
                ldsm_x4(kl0, kl1, kl2, kl3, stb + AT_B + ko);
                mma_f16(S[2 * np + 0], qf[k16], kh0, kh1);
                mma_f16(S[2 * np + 1], qf[k16], kh2, kh3);
                mma_f16(S[2 * np + 0], qf[k16], kl0, kl1);
                mma_f16(S[2 * np + 1], qf[k16], kl2, kl3);
            }
        }

        const int kb = kt * 64;
        if (kt >= 2 * Qi) {
#pragma unroll
            for (int j = 0; j < 8; j++) {
#pragma unroll
                for (int cc = 0; cc < 2; cc++) {
                    int key = kb + 8 * j + 2 * t4 + cc;
                    if (key > myrow)     S[j][cc]     = -INFINITY;
                    if (key > myrow + 8) S[j][2 + cc] = -INFINITY;
                }
            }
        }

        // ---- online softmax ----
#pragma unroll
        for (int r = 0; r < 2; r++) {
            float mx = S[0][2 * r];
#pragma unroll
            for (int j = 0; j < 8; j++) {
                mx = fmaxf(mx, S[j][2 * r]);
                mx = fmaxf(mx, S[j][2 * r + 1]);
            }
            mx = fmaxf(mx, __shfl_xor_sync(0xffffffffu, mx, 1));
            mx = fmaxf(mx, __shfl_xor_sync(0xffffffffu, mx, 2));
            float mn = fmaxf(mrow[r], mx);
            float alpha = __expf(mrow[r] - mn);
            float rs = 0.0f;
#pragma unroll
            for (int j = 0; j < 8; j++) {
                float p0 = __expf(S[j][2 * r] - mn);
                float p1 = __expf(S[j][2 * r + 1] - mn);
                S[j][2 * r] = p0;
                S[j][2 * r + 1] = p1;
                rs += p0 + p1;
            }
            rs += __shfl_xor_sync(0xffffffffu, rs, 1);
            rs += __shfl_xor_sync(0xffffffffu, rs, 2);
            lrow[r] = lrow[r] * alpha + rs;
            mrow[r] = mn;
#pragma unroll
            for (int t = 0; t < 8; t++) {
                ctx[t][2 * r] *= alpha;
                ctx[t][2 * r + 1] *= alpha;
            }
        }

        // ---- ctx += P·Vh + P·Vl (P single fp16) ----
#pragma unroll
        for (int j2 = 0; j2 < 4; j2++) {
            uint32_t pf[4];
            pf[0] = h2pack(S[2 * j2][0],     S[2 * j2][1]);
            pf[1] = h2pack(S[2 * j2][2],     S[2 * j2][3]);
            pf[2] = h2pack(S[2 * j2 + 1][0], S[2 * j2 + 1][1]);
            pf[3] = h2pack(S[2 * j2 + 1][2], S[2 * j2 + 1][3]);
#pragma unroll
            for (int np = 0; np < 4; np++) {
                uint32_t vo = aoff(16 * np + lr + (lg >> 1) * 8, 2 * j2 + (lg & 1));
                uint32_t vh0, vh1, vh2, vh3, vl0, vl1, vl2, vl3;
                ldsm_x4(vh0, vh1, vh2, vh3, stb + 2 * AT_B + vo);
                ldsm_x4(vl0, vl1, vl2, vl3, stb + 3 * AT_B + vo);
                mma_f16(ctx[2 * np + 0], pf, vh0, vh1);
                mma_f16(ctx[2 * np + 1], pf, vh2, vh3);
                mma_f16(ctx[2 * np + 0], pf, vl0, vl1);
                mma_f16(ctx[2 * np + 1], pf, vl2, vl3);
            }
        }

        __syncthreads();
        if (kt + 2 < ntiles) {
            att_load_kv(stb, hb, (kt + 2) * 64, tid);
            cpa_commit();
        }
    }

    // ---- epilogue: normalize, convert to fp16, store ctx ----
#pragma unroll
    for (int r = 0; r < 2; r++) {
        float inv = 1.0f / lrow[r];
        int srow = q0 + 16 * wid + g + 8 * r;
        size_t base = ((size_t)b * SS + srow) * DD + h * DHD;
#pragma unroll
        for (int t = 0; t < 8; t++) {
            size_t idx = base + 8 * t + 2 * t4;
            *reinterpret_cast<uint32_t*>(&g_ch[idx]) =
                h2pack(ctx[t][2 * r] * inv, ctx[t][2 * r + 1] * inv);
        }
    }
}

// ---------------------------------------------------------------------------
extern "C" void kernel_launch(void* const* d_in, const int* in_sizes, int n_in,
                              void* d_out, int out_size) {
    const float* x  = (const float*)d_in[0];
    const float* Wq = (const float*)d_in[1];
    const float* bq = (const float*)d_in[2];
    const float* Wk = (const float*)d_in[3];
    const float* bk = (const float*)d_in[4];
    const float* Wv = (const float*)d_in[5];
    const float* bv = (const float*)d_in[6];
    const float* Wo = (const float*)d_in[7];
    const float* bo = (const float*)d_in[8];
    float* out = (float*)d_out;

    __half *pxh, *pch;
    cudaGetSymbolAddress((void**)&pxh, g_xh);
    cudaGetSymbolAddress((void**)&pch, g_ch);

    cudaFuncSetAttribute(gemm_tc_kernel<0>, cudaFuncAttributeMaxDynamicSharedMemorySize, GEMM_SMEM);
    cudaFuncSetAttribute(gemm_tc_kernel<1>, cudaFuncAttributeMaxDynamicSharedMemorySize, GEMM_SMEM);
    cudaFuncSetAttribute(attn_kernel, cudaFuncAttributeMaxDynamicSharedMemorySize, ATT_SMEM);

    convert_x_kernel<<<(MROWS * DD / 4) / 256, 256>>>(x, pxh);

    dim3 tgrid(DD / 32, DD / 32, 4);
    convert_wT_kernel<<<tgrid, 256>>>(Wq, Wk, Wv, Wo);

    dim3 ggrid(DD / BN, MROWS / BM, 3);
    gemm_tc_kernel<1><<<ggrid, 256, GEMM_SMEM>>>(pxh, bq, bk, bv, nullptr);

    dim3 agrid(SS / 128, HN, BB);
    attn_kernel<<<agrid, 256, ATT_SMEM>>>();

    dim3 ogrid(DD / BN, MROWS / BM, 1);
    gemm_tc_kernel<0><<<ogrid, 256, GEMM_SMEM>>>(pch, bo, nullptr, nullptr, out);
}